// round 4
// baseline (speedup 1.0000x reference)
#include <cuda_runtime.h>
#include <math.h>

// Problem constants
#define BB 128
#define CC 768
#define NN 196
#define DD 128
#define TK 8
#define NC 16                      // candidate count for exact re-rank
#define M_NODES (BB * NN)          // 25088
#define NE      (M_NODES * TK)     // 200704

// Scratch (device globals; no allocations allowed)
__device__ float  g_nrm[M_NODES * DD];          // normalized nodes (fp32, candidate stage)
__device__ float  g_sim[BB * NN * NN];          // similarity (fp32, candidate stage)
__device__ double g_dinv[M_NODES];              // double 1/||node||
__device__ int    g_cand[M_NODES * NC];         // top-16 fp32 candidates
__device__ int    g_adj[NE];                    // final top-8 indices
__device__ float  g_table[27 * 27 * DD];        // pos-MLP table
__device__ float  g_c1[M_NODES * DD];           // nodes @ We1[0:128]
__device__ float  g_c2[M_NODES * DD];           // nodes @ We1[128:256]
__device__ float  g_c3[27 * 27 * DD];           // table @ We1[256:384] + be1

__device__ __forceinline__ float gelu_exact(float x) {
    return 0.5f * x * (1.0f + erff(x * 0.70710678118654752440f));
}
__device__ __forceinline__ double gelu_exact_d(double x) {
    return 0.5 * x * (1.0 + erf(x * 0.7071067811865475244));
}

// ---------------------------------------------------------------------------
// Kernel 1: pos-MLP table. disp has only 27x27 distinct values (i/13 grid).
// ---------------------------------------------------------------------------
__global__ void pos_table_kernel(const float* __restrict__ Wp1, const float* __restrict__ bp1,
                                 const float* __restrict__ Wp2, const float* __restrict__ bp2) {
    __shared__ float h[64];
    int idx = blockIdx.x;
    float dy = (float)(idx / 27 - 13) * (1.0f / 13.0f);
    float dx = (float)(idx % 27 - 13) * (1.0f / 13.0f);
    int t = threadIdx.x;
    if (t < 64) {
        float v = dy * Wp1[t] + dx * Wp1[64 + t] + bp1[t];
        h[t] = gelu_exact(v);
    }
    __syncthreads();
    float acc = bp2[t];
    #pragma unroll 8
    for (int i = 0; i < 64; i++) acc += h[i] * Wp2[i * DD + t];
    g_table[idx * DD + t] = acc;
}

// ---------------------------------------------------------------------------
// Kernel 2: nodes = GELU(LN(tokens @ W_node + b_node)).
// Chunked-double accumulation: fp32 partials over 48 k-elems, DADD'd into
// doubles. Tail (LN + GELU) in double, rounded once to fp32.
// ---------------------------------------------------------------------------
__global__ void node_kernel(const float* __restrict__ feat, const float* __restrict__ Wn,
                            const float* __restrict__ bnode, const float* __restrict__ ln_g,
                            const float* __restrict__ ln_b, float* __restrict__ nodes_out) {
    __shared__ float As[16][65];
    __shared__ float4 Bs[16 * 32];
    __shared__ float Cs[64][128];
    __shared__ int s_base[64];
    int tid = threadIdx.x;
    int m0 = blockIdx.x * 64;
    if (tid < 64) {
        int m = m0 + tid;
        int b = m / NN, n = m % NN;
        s_base[tid] = b * (CC * NN) + n;
    }
    int tx = tid & 31, ty = tid >> 5;
    double dacc[8][4];
    #pragma unroll
    for (int i = 0; i < 8; i++)
        #pragma unroll
        for (int q = 0; q < 4; q++) dacc[i][q] = 0.0;
    float acc16[8][4];
    #pragma unroll
    for (int i = 0; i < 8; i++)
        #pragma unroll
        for (int q = 0; q < 4; q++) acc16[i][q] = 0.f;
    int cnt = 0;
    __syncthreads();
    for (int k0 = 0; k0 < CC; k0 += 16) {
        #pragma unroll
        for (int i = 0; i < 4; i++) {
            int e = tid + i * 256;
            int r = e & 63, cc = e >> 6;
            As[cc][r] = feat[s_base[r] + (k0 + cc) * NN];
        }
        const float4* Wg = (const float4*)(Wn + k0 * DD);
        Bs[tid] = Wg[tid];
        Bs[tid + 256] = Wg[tid + 256];
        __syncthreads();
        #pragma unroll
        for (int cc = 0; cc < 16; cc++) {
            float4 bv = Bs[cc * 32 + tx];
            #pragma unroll
            for (int i = 0; i < 8; i++) {
                float a = As[cc][ty + 8 * i];
                acc16[i][0] += a * bv.x; acc16[i][1] += a * bv.y;
                acc16[i][2] += a * bv.z; acc16[i][3] += a * bv.w;
            }
        }
        if (++cnt == 3) {
            cnt = 0;
            #pragma unroll
            for (int i = 0; i < 8; i++)
                #pragma unroll
                for (int q = 0; q < 4; q++) {
                    dacc[i][q] += (double)acc16[i][q];
                    acc16[i][q] = 0.f;
                }
        }
        __syncthreads();
    }
    float4 bb = ((const float4*)bnode)[tx];
    #pragma unroll
    for (int i = 0; i < 8; i++) {
        int r = ty + 8 * i;
        Cs[r][tx * 4 + 0] = (float)(dacc[i][0] + (double)bb.x);
        Cs[r][tx * 4 + 1] = (float)(dacc[i][1] + (double)bb.y);
        Cs[r][tx * 4 + 2] = (float)(dacc[i][2] + (double)bb.z);
        Cs[r][tx * 4 + 3] = (float)(dacc[i][3] + (double)bb.w);
    }
    __syncthreads();
    // LayerNorm + GELU in double, one warp per row
    int lane = tx, w = ty;
    for (int rr = 0; rr < 8; rr++) {
        int r = w + 8 * rr;
        double x[4];
        double s = 0.0;
        #pragma unroll
        for (int q = 0; q < 4; q++) { x[q] = (double)Cs[r][lane + 32 * q]; s += x[q]; }
        #pragma unroll
        for (int o = 16; o > 0; o >>= 1) s += __shfl_xor_sync(~0u, s, o);
        double mu = s * (1.0 / 128.0);
        double vs = 0.0;
        #pragma unroll
        for (int q = 0; q < 4; q++) { double d = x[q] - mu; vs += d * d; }
        #pragma unroll
        for (int o = 16; o > 0; o >>= 1) vs += __shfl_xor_sync(~0u, vs, o);
        double rs = 1.0 / sqrt(vs * (1.0 / 128.0) + 1e-5);
        int row = m0 + r;
        #pragma unroll
        for (int q = 0; q < 4; q++) {
            int d = lane + 32 * q;
            double y = (x[q] - mu) * rs * (double)ln_g[d] + (double)ln_b[d];
            nodes_out[(size_t)row * DD + d] = (float)gelu_exact_d(y);
        }
    }
}

// ---------------------------------------------------------------------------
// Kernel 3: L2-normalize nodes (warp per row).
// ---------------------------------------------------------------------------
__global__ void norm_kernel(const float* __restrict__ nodes) {
    int w = (blockIdx.x * blockDim.x + threadIdx.x) >> 5;
    int lane = threadIdx.x & 31;
    if (w >= M_NODES) return;
    const float4* rp = (const float4*)(nodes + (size_t)w * DD);
    float4 v = rp[lane];
    double s = (double)v.x * v.x + (double)v.y * v.y + (double)v.z * v.z + (double)v.w * v.w;
    #pragma unroll
    for (int o = 16; o > 0; o >>= 1) s += __shfl_xor_sync(~0u, s, o);
    double dinv = 1.0 / fmax(sqrt(s), 1e-12);
    if (lane == 0) g_dinv[w] = dinv;
    float inv = (float)dinv;
    ((float4*)(g_nrm + (size_t)w * DD))[lane] =
        make_float4(v.x * inv, v.y * inv, v.z * inv, v.w * inv);
}

// ---------------------------------------------------------------------------
// Kernel 4: sim = nrm @ nrm^T per batch. 32x32 tile, 64 threads, 4x4 micro,
// float4 LDS, K chunked by 32.
// ---------------------------------------------------------------------------
__global__ void sim_kernel() {
    __shared__ float As[32][36];
    __shared__ float Bs[32][36];
    int tid = threadIdx.x;
    const float* base = g_nrm + (size_t)blockIdx.z * (NN * DD);
    int by = blockIdx.y, bx = blockIdx.x;
    int tx = tid & 7, ty = tid >> 3;
    float acc[4][4] = {};
    for (int k0 = 0; k0 < 128; k0 += 32) {
        #pragma unroll
        for (int it = 0; it < 4; it++) {
            int idx = tid + it * 64;                 // 0..255
            int r = idx >> 3, kg = (idx & 7) * 4;
            int na = by * 32 + r;
            float4 v = (na < NN) ? *(const float4*)(base + (size_t)na * DD + k0 + kg)
                                 : make_float4(0.f, 0.f, 0.f, 0.f);
            As[kg + 0][r] = v.x; As[kg + 1][r] = v.y; As[kg + 2][r] = v.z; As[kg + 3][r] = v.w;
            int ma = bx * 32 + r;
            float4 u = (ma < NN) ? *(const float4*)(base + (size_t)ma * DD + k0 + kg)
                                 : make_float4(0.f, 0.f, 0.f, 0.f);
            Bs[kg + 0][r] = u.x; Bs[kg + 1][r] = u.y; Bs[kg + 2][r] = u.z; Bs[kg + 3][r] = u.w;
        }
        __syncthreads();
        #pragma unroll
        for (int k = 0; k < 32; k++) {
            float4 a = *(float4*)&As[k][ty * 4];
            float4 b = *(float4*)&Bs[k][tx * 4];
            float av[4] = {a.x, a.y, a.z, a.w};
            float bv[4] = {b.x, b.y, b.z, b.w};
            #pragma unroll
            for (int i = 0; i < 4; i++)
                #pragma unroll
                for (int j = 0; j < 4; j++) acc[i][j] += av[i] * bv[j];
        }
        __syncthreads();
    }
    float* simb = g_sim + (size_t)blockIdx.z * (NN * NN);
    #pragma unroll
    for (int i = 0; i < 4; i++) {
        int n0 = by * 32 + ty * 4 + i;
        if (n0 >= NN) break;
        int mcol = bx * 32 + tx * 4;
        if (mcol + 3 < NN) {
            *(float4*)(simb + n0 * NN + mcol) =
                make_float4(acc[i][0], acc[i][1], acc[i][2], acc[i][3]);
        } else {
            #pragma unroll
            for (int j = 0; j < 4; j++)
                if (mcol + j < NN) simb[n0 * NN + mcol + j] = acc[i][j];
        }
    }
}

// ---------------------------------------------------------------------------
// Kernel 5a: fp32 top-16 candidates per row (8-slot safety margin).
// ---------------------------------------------------------------------------
__global__ void cand_kernel() {
    int t = blockIdx.x * blockDim.x + threadIdx.x;
    if (t >= M_NODES) return;
    int b = t / NN, n = t % NN;
    const float* row = g_sim + (size_t)b * (NN * NN) + n * NN;
    float val[NC]; int idx[NC];
    #pragma unroll
    for (int i = 0; i < NC; i++) { val[i] = -1e30f; idx[i] = 0; }
    for (int m4 = 0; m4 < NN; m4 += 4) {
        float4 vv = *(const float4*)(row + m4);
        float vs[4] = {vv.x, vv.y, vv.z, vv.w};
        #pragma unroll
        for (int q = 0; q < 4; q++) {
            int m = m4 + q;
            if (m == n) continue;
            float v = vs[q];
            if (v > val[NC - 1]) {
                int i = NC - 1;
                while (i > 0 && v > val[i - 1]) {
                    val[i] = val[i - 1]; idx[i] = idx[i - 1]; i--;
                }
                val[i] = v; idx[i] = m;
            }
        }
    }
    #pragma unroll
    for (int k = 0; k < NC; k++) g_cand[t * NC + k] = idx[k];
}

// ---------------------------------------------------------------------------
// Kernel 5b: exact re-rank in double; fp32 round; stable sort; emit top-8.
// ---------------------------------------------------------------------------
__global__ void refine_kernel(const float* __restrict__ nodes, float* __restrict__ adj_out) {
    __shared__ float skey[8][NC];
    __shared__ int   sidx[8][NC];
    int wip = threadIdx.x >> 5;
    int lane = threadIdx.x & 31;
    int t = blockIdx.x * 8 + wip;
    if (t >= M_NODES) return;
    int b = t / NN;
    int rowbase = b * NN;
    double dinv_n = g_dinv[t];
    float4 av = ((const float4*)(nodes + (size_t)t * DD))[lane];
    int myc = (lane < NC) ? g_cand[t * NC + lane] : 0;
    #pragma unroll
    for (int c = 0; c < NC; c++) {
        int j = __shfl_sync(~0u, myc, c);
        float4 bv = ((const float4*)(nodes + (size_t)(rowbase + j) * DD))[lane];
        double p = (double)av.x * bv.x + (double)av.y * bv.y
                 + (double)av.z * bv.z + (double)av.w * bv.w;
        #pragma unroll
        for (int o = 16; o > 0; o >>= 1) p += __shfl_xor_sync(~0u, p, o);
        if (lane == c) {
            double sim = p * dinv_n * g_dinv[rowbase + j];
            skey[wip][c] = (float)sim;
            sidx[wip][c] = j;
        }
    }
    __syncwarp();
    if (lane == 0) {
        float kv[NC]; int ki[NC];
        #pragma unroll
        for (int i = 0; i < NC; i++) { kv[i] = skey[wip][i]; ki[i] = sidx[wip][i]; }
        #pragma unroll
        for (int i = 1; i < NC; i++) {
            float v = kv[i]; int id = ki[i];
            int p = i - 1;
            while (p >= 0 && (kv[p] < v || (kv[p] == v && ki[p] > id))) {
                kv[p + 1] = kv[p]; ki[p + 1] = ki[p]; p--;
            }
            kv[p + 1] = v; ki[p + 1] = id;
        }
        #pragma unroll
        for (int k = 0; k < TK; k++) {
            g_adj[t * TK + k] = ki[k];
            adj_out[t * TK + k] = (float)ki[k];
        }
    }
}

// ---------------------------------------------------------------------------
// Kernel 6: C1 = nodes @ We1[0:128], C2 = nodes @ We1[128:256].
// 128x128 tile, 256 threads, 8x8 micro. blockIdx.y selects segment.
// ---------------------------------------------------------------------------
__global__ void cgemm_kernel(const float* __restrict__ nodes, const float* __restrict__ We1) {
    __shared__ float As[16][132];
    __shared__ float Bs[16][128];
    int tid = threadIdx.x;
    int m0 = blockIdx.x * 128;
    int seg = blockIdx.y;
    float* C = seg ? g_c2 : g_c1;
    const float* W = We1 + (size_t)seg * 128 * DD;
    int tx = tid & 15, ty = tid >> 4;
    float acc[8][8] = {};
    for (int k0 = 0; k0 < 128; k0 += 16) {
        #pragma unroll
        for (int q = 0; q < 2; q++) {
            int idx = tid + q * 256;
            int r = idx >> 2, kg = (idx & 3) * 4;
            float4 v = *(const float4*)(nodes + (size_t)(m0 + r) * DD + k0 + kg);
            As[kg + 0][r] = v.x; As[kg + 1][r] = v.y; As[kg + 2][r] = v.z; As[kg + 3][r] = v.w;
        }
        #pragma unroll
        for (int q = 0; q < 2; q++) {
            int idx = tid + q * 256;
            int kk = idx >> 5, cg = (idx & 31) * 4;
            *(float4*)&Bs[kk][cg] = *(const float4*)(W + (size_t)(k0 + kk) * DD + cg);
        }
        __syncthreads();
        #pragma unroll
        for (int kc = 0; kc < 16; kc++) {
            float4 a0 = *(float4*)&As[kc][ty * 4];
            float4 a1 = *(float4*)&As[kc][ty * 4 + 64];
            float4 b0 = *(float4*)&Bs[kc][tx * 4];
            float4 b1 = *(float4*)&Bs[kc][tx * 4 + 64];
            float av[8] = {a0.x, a0.y, a0.z, a0.w, a1.x, a1.y, a1.z, a1.w};
            float bv[8] = {b0.x, b0.y, b0.z, b0.w, b1.x, b1.y, b1.z, b1.w};
            #pragma unroll
            for (int i = 0; i < 8; i++)
                #pragma unroll
                for (int j = 0; j < 8; j++) acc[i][j] += av[i] * bv[j];
        }
        __syncthreads();
    }
    #pragma unroll
    for (int i = 0; i < 8; i++) {
        int row = m0 + ((i < 4) ? (ty * 4 + i) : (64 + ty * 4 + i - 4));
        *(float4*)(C + (size_t)row * DD + tx * 4) =
            make_float4(acc[i][0], acc[i][1], acc[i][2], acc[i][3]);
        *(float4*)(C + (size_t)row * DD + tx * 4 + 64) =
            make_float4(acc[i][4], acc[i][5], acc[i][6], acc[i][7]);
    }
}

// ---------------------------------------------------------------------------
// Kernel 7: C3 = table @ We1[256:384] + be1 (729 rows, tiny).
// ---------------------------------------------------------------------------
__global__ void c3_kernel(const float* __restrict__ We1, const float* __restrict__ be1) {
    __shared__ float ts[128];
    int row = blockIdx.x, t = threadIdx.x;
    ts[t] = g_table[row * DD + t];
    __syncthreads();
    float acc = be1[t];
    const float* W = We1 + (size_t)256 * DD;
    #pragma unroll 8
    for (int k = 0; k < 128; k++) acc += ts[k] * W[k * DD + t];
    g_c3[row * DD + t] = acc;
}

// ---------------------------------------------------------------------------
// Kernel 8: fused edges = GELU(C1[n] + C2[adj] + C3[disp]) @ We2 + be2.
// 128 edge-rows x 128 cols per block; A tile built on the fly per k-chunk.
// ---------------------------------------------------------------------------
__global__ void edge_fused_kernel(const float* __restrict__ We2, const float* __restrict__ be2,
                                  float* __restrict__ edges_out) {
    __shared__ float As[16][132];
    __shared__ float Bs[16][128];
    __shared__ int s1[128], s2[128], s3[128];
    int tid = threadIdx.x;
    int m0 = blockIdx.x * 128;
    if (tid < 128) {
        int e = m0 + tid;
        int bn = e >> 3;
        int b = bn / NN, n = bn - b * NN;
        int j = g_adj[e];
        s1[tid] = bn * DD;
        s2[tid] = (b * NN + j) * DD;
        int rn = n / 14, cn = n % 14, rj = j / 14, cj = j % 14;
        s3[tid] = ((rj - rn + 13) * 27 + (cj - cn + 13)) * DD;
    }
    __syncthreads();
    int tx = tid & 15, ty = tid >> 4;
    int gr = tid >> 1, gc = (tid & 1) * 8;      // gather: row, col-group of 8
    float acc[8][8] = {};
    for (int k0 = 0; k0 < 128; k0 += 16) {
        {
            const float* p1 = g_c1 + s1[gr] + k0 + gc;
            const float* p2 = g_c2 + s2[gr] + k0 + gc;
            const float* p3 = g_c3 + s3[gr] + k0 + gc;
            #pragma unroll
            for (int q = 0; q < 2; q++) {
                float4 v1 = *(const float4*)(p1 + q * 4);
                float4 v2 = *(const float4*)(p2 + q * 4);
                float4 v3 = *(const float4*)(p3 + q * 4);
                As[gc + q * 4 + 0][gr] = gelu_exact(v1.x + v2.x + v3.x);
                As[gc + q * 4 + 1][gr] = gelu_exact(v1.y + v2.y + v3.y);
                As[gc + q * 4 + 2][gr] = gelu_exact(v1.z + v2.z + v3.z);
                As[gc + q * 4 + 3][gr] = gelu_exact(v1.w + v2.w + v3.w);
            }
        }
        #pragma unroll
        for (int q = 0; q < 2; q++) {
            int idx = tid + q * 256;
            int kk = idx >> 5, cg = (idx & 31) * 4;
            *(float4*)&Bs[kk][cg] = *(const float4*)(We2 + (size_t)(k0 + kk) * DD + cg);
        }
        __syncthreads();
        #pragma unroll
        for (int kc = 0; kc < 16; kc++) {
            float4 a0 = *(float4*)&As[kc][ty * 4];
            float4 a1 = *(float4*)&As[kc][ty * 4 + 64];
            float4 b0 = *(float4*)&Bs[kc][tx * 4];
            float4 b1 = *(float4*)&Bs[kc][tx * 4 + 64];
            float av[8] = {a0.x, a0.y, a0.z, a0.w, a1.x, a1.y, a1.z, a1.w};
            float bv[8] = {b0.x, b0.y, b0.z, b0.w, b1.x, b1.y, b1.z, b1.w};
            #pragma unroll
            for (int i = 0; i < 8; i++)
                #pragma unroll
                for (int j = 0; j < 8; j++) acc[i][j] += av[i] * bv[j];
        }
        __syncthreads();
    }
    float4 bb0 = *(const float4*)(be2 + tx * 4);
    float4 bb1 = *(const float4*)(be2 + tx * 4 + 64);
    #pragma unroll
    for (int i = 0; i < 8; i++) {
        int row = m0 + ((i < 4) ? (ty * 4 + i) : (64 + ty * 4 + i - 4));
        *(float4*)(edges_out + (size_t)row * DD + tx * 4) =
            make_float4(acc[i][0] + bb0.x, acc[i][1] + bb0.y,
                        acc[i][2] + bb0.z, acc[i][3] + bb0.w);
        *(float4*)(edges_out + (size_t)row * DD + tx * 4 + 64) =
            make_float4(acc[i][4] + bb1.x, acc[i][5] + bb1.y,
                        acc[i][6] + bb1.z, acc[i][7] + bb1.w);
    }
}

// ---------------------------------------------------------------------------
extern "C" void kernel_launch(void* const* d_in, const int* in_sizes, int n_in,
                              void* d_out, int out_size) {
    const float* feat = (const float*)d_in[0];
    const float* Wn   = (const float*)d_in[1];
    const float* bn   = (const float*)d_in[2];
    const float* lng  = (const float*)d_in[3];
    const float* lnb  = (const float*)d_in[4];
    const float* Wp1  = (const float*)d_in[5];
    const float* bp1  = (const float*)d_in[6];
    const float* Wp2  = (const float*)d_in[7];
    const float* bp2  = (const float*)d_in[8];
    const float* We1  = (const float*)d_in[9];
    const float* be1  = (const float*)d_in[10];
    const float* We2  = (const float*)d_in[11];
    const float* be2  = (const float*)d_in[12];

    float* out = (float*)d_out;
    float* nodes_out = out;                                   // B*N*D
    float* edges_out = out + (size_t)M_NODES * DD;            // B*N*K*D
    float* adj_out   = edges_out + (size_t)NE * DD;           // B*N*K

    pos_table_kernel<<<729, 128>>>(Wp1, bp1, Wp2, bp2);
    node_kernel<<<M_NODES / 64, 256>>>(feat, Wn, bn, lng, lnb, nodes_out);
    norm_kernel<<<(M_NODES * 32) / 256, 256>>>(nodes_out);
    sim_kernel<<<dim3(7, 7, BB), 64>>>();
    cand_kernel<<<(M_NODES + 255) / 256, 256>>>();
    refine_kernel<<<(M_NODES + 7) / 8, 256>>>(nodes_out, adj_out);
    cgemm_kernel<<<dim3(M_NODES / 128, 2), 256>>>(nodes_out, We1);
    c3_kernel<<<729, 128>>>(We1, be1);
    edge_fused_kernel<<<NE / 128, 256>>>(We2, be2, edges_out);
}

// round 7
// speedup vs baseline: 1.5904x; 1.5904x over previous
#include <cuda_runtime.h>
#include <math.h>

// Problem constants
#define BB 128
#define CC 768
#define NN 196
#define DD 128
#define TK 8
#define NC 16                      // candidate count for exact re-rank
#define M_NODES (BB * NN)          // 25088
#define NE      (M_NODES * TK)     // 200704

// Scratch (device globals; no allocations allowed)
__device__ float  g_nrm[M_NODES * DD];          // normalized nodes (fp32, candidate stage)
__device__ float  g_sim[BB * NN * NN];          // similarity (fp32, candidate stage)
__device__ double g_dinv[M_NODES];              // double 1/||node||
__device__ int    g_cand[M_NODES * NC];         // top-16 fp32 candidates
__device__ int    g_adj[NE];                    // final top-8 indices
__device__ float  g_table[27 * 27 * DD];        // pos-MLP table
__device__ float  g_c1[M_NODES * DD];           // nodes @ We1[0:128]
__device__ float  g_c2[M_NODES * DD];           // nodes @ We1[128:256]
__device__ float  g_c3[27 * 27 * DD];           // table @ We1[256:384] + be1

__device__ __forceinline__ float gelu_exact(float x) {
    return 0.5f * x * (1.0f + erff(x * 0.70710678118654752440f));
}
__device__ __forceinline__ double gelu_exact_d(double x) {
    return 0.5 * x * (1.0 + erf(x * 0.7071067811865475244));
}

// ---------------------------------------------------------------------------
// Kernel 1: pos-MLP table. disp has only 27x27 distinct values (i/13 grid).
// ---------------------------------------------------------------------------
__global__ void pos_table_kernel(const float* __restrict__ Wp1, const float* __restrict__ bp1,
                                 const float* __restrict__ Wp2, const float* __restrict__ bp2) {
    __shared__ float h[64];
    int idx = blockIdx.x;
    float dy = (float)(idx / 27 - 13) * (1.0f / 13.0f);
    float dx = (float)(idx % 27 - 13) * (1.0f / 13.0f);
    int t = threadIdx.x;
    if (t < 64) {
        float v = dy * Wp1[t] + dx * Wp1[64 + t] + bp1[t];
        h[t] = gelu_exact(v);
    }
    __syncthreads();
    float acc = bp2[t];
    #pragma unroll 8
    for (int i = 0; i < 64; i++) acc += h[i] * Wp2[i * DD + t];
    g_table[idx * DD + t] = acc;
}

// ---------------------------------------------------------------------------
// Kernel 2: nodes = GELU(LN(tokens @ W_node + b_node)).
// Chunked-double accumulation (48 k-elems per DADD). LN+GELU in double.
// ---------------------------------------------------------------------------
__global__ void node_kernel(const float* __restrict__ feat, const float* __restrict__ Wn,
                            const float* __restrict__ bnode, const float* __restrict__ ln_g,
                            const float* __restrict__ ln_b, float* __restrict__ nodes_out) {
    __shared__ float As[16][65];
    __shared__ float4 Bs[16 * 32];
    __shared__ float Cs[64][128];
    __shared__ int s_base[64];
    int tid = threadIdx.x;
    int m0 = blockIdx.x * 64;
    if (tid < 64) {
        int m = m0 + tid;
        int b = m / NN, n = m % NN;
        s_base[tid] = b * (CC * NN) + n;
    }
    int tx = tid & 31, ty = tid >> 5;
    double dacc[8][4];
    #pragma unroll
    for (int i = 0; i < 8; i++)
        #pragma unroll
        for (int q = 0; q < 4; q++) dacc[i][q] = 0.0;
    float acc16[8][4];
    #pragma unroll
    for (int i = 0; i < 8; i++)
        #pragma unroll
        for (int q = 0; q < 4; q++) acc16[i][q] = 0.f;
    int cnt = 0;
    __syncthreads();
    for (int k0 = 0; k0 < CC; k0 += 16) {
        #pragma unroll
        for (int i = 0; i < 4; i++) {
            int e = tid + i * 256;
            int r = e & 63, cc = e >> 6;
            As[cc][r] = feat[s_base[r] + (k0 + cc) * NN];
        }
        const float4* Wg = (const float4*)(Wn + k0 * DD);
        Bs[tid] = Wg[tid];
        Bs[tid + 256] = Wg[tid + 256];
        __syncthreads();
        #pragma unroll
        for (int cc = 0; cc < 16; cc++) {
            float4 bv = Bs[cc * 32 + tx];
            #pragma unroll
            for (int i = 0; i < 8; i++) {
                float a = As[cc][ty + 8 * i];
                acc16[i][0] += a * bv.x; acc16[i][1] += a * bv.y;
                acc16[i][2] += a * bv.z; acc16[i][3] += a * bv.w;
            }
        }
        if (++cnt == 3) {
            cnt = 0;
            #pragma unroll
            for (int i = 0; i < 8; i++)
                #pragma unroll
                for (int q = 0; q < 4; q++) {
                    dacc[i][q] += (double)acc16[i][q];
                    acc16[i][q] = 0.f;
                }
        }
        __syncthreads();
    }
    float4 bb = ((const float4*)bnode)[tx];
    #pragma unroll
    for (int i = 0; i < 8; i++) {
        int r = ty + 8 * i;
        Cs[r][tx * 4 + 0] = (float)(dacc[i][0] + (double)bb.x);
        Cs[r][tx * 4 + 1] = (float)(dacc[i][1] + (double)bb.y);
        Cs[r][tx * 4 + 2] = (float)(dacc[i][2] + (double)bb.z);
        Cs[r][tx * 4 + 3] = (float)(dacc[i][3] + (double)bb.w);
    }
    __syncthreads();
    // LayerNorm + GELU in double, one warp per row
    int lane = tx, w = ty;
    for (int rr = 0; rr < 8; rr++) {
        int r = w + 8 * rr;
        double x[4];
        double s = 0.0;
        #pragma unroll
        for (int q = 0; q < 4; q++) { x[q] = (double)Cs[r][lane + 32 * q]; s += x[q]; }
        #pragma unroll
        for (int o = 16; o > 0; o >>= 1) s += __shfl_xor_sync(~0u, s, o);
        double mu = s * (1.0 / 128.0);
        double vs = 0.0;
        #pragma unroll
        for (int q = 0; q < 4; q++) { double d = x[q] - mu; vs += d * d; }
        #pragma unroll
        for (int o = 16; o > 0; o >>= 1) vs += __shfl_xor_sync(~0u, vs, o);
        double rs = 1.0 / sqrt(vs * (1.0 / 128.0) + 1e-5);
        int row = m0 + r;
        #pragma unroll
        for (int q = 0; q < 4; q++) {
            int d = lane + 32 * q;
            double y = (x[q] - mu) * rs * (double)ln_g[d] + (double)ln_b[d];
            nodes_out[(size_t)row * DD + d] = (float)gelu_exact_d(y);
        }
    }
}

// ---------------------------------------------------------------------------
// Kernel 3: L2-normalize nodes (warp per row).
// ---------------------------------------------------------------------------
__global__ void norm_kernel(const float* __restrict__ nodes) {
    int w = (blockIdx.x * blockDim.x + threadIdx.x) >> 5;
    int lane = threadIdx.x & 31;
    if (w >= M_NODES) return;
    const float4* rp = (const float4*)(nodes + (size_t)w * DD);
    float4 v = rp[lane];
    double s = (double)v.x * v.x + (double)v.y * v.y + (double)v.z * v.z + (double)v.w * v.w;
    #pragma unroll
    for (int o = 16; o > 0; o >>= 1) s += __shfl_xor_sync(~0u, s, o);
    double dinv = 1.0 / fmax(sqrt(s), 1e-12);
    if (lane == 0) g_dinv[w] = dinv;
    float inv = (float)dinv;
    ((float4*)(g_nrm + (size_t)w * DD))[lane] =
        make_float4(v.x * inv, v.y * inv, v.z * inv, v.w * inv);
}

// ---------------------------------------------------------------------------
// Kernel 4: sim = nrm @ nrm^T per batch. 32x32 tile, 64 threads, 4x4 micro.
// ---------------------------------------------------------------------------
__global__ void sim_kernel() {
    __shared__ float As[32][36];
    __shared__ float Bs[32][36];
    int tid = threadIdx.x;
    const float* base = g_nrm + (size_t)blockIdx.z * (NN * DD);
    int by = blockIdx.y, bx = blockIdx.x;
    int tx = tid & 7, ty = tid >> 3;
    float acc[4][4] = {};
    for (int k0 = 0; k0 < 128; k0 += 32) {
        #pragma unroll
        for (int it = 0; it < 4; it++) {
            int idx = tid + it * 64;                 // 0..255
            int r = idx >> 3, kg = (idx & 7) * 4;
            int na = by * 32 + r;
            float4 v = (na < NN) ? *(const float4*)(base + (size_t)na * DD + k0 + kg)
                                 : make_float4(0.f, 0.f, 0.f, 0.f);
            As[kg + 0][r] = v.x; As[kg + 1][r] = v.y; As[kg + 2][r] = v.z; As[kg + 3][r] = v.w;
            int ma = bx * 32 + r;
            float4 u = (ma < NN) ? *(const float4*)(base + (size_t)ma * DD + k0 + kg)
                                 : make_float4(0.f, 0.f, 0.f, 0.f);
            Bs[kg + 0][r] = u.x; Bs[kg + 1][r] = u.y; Bs[kg + 2][r] = u.z; Bs[kg + 3][r] = u.w;
        }
        __syncthreads();
        #pragma unroll
        for (int k = 0; k < 32; k++) {
            float4 a = *(float4*)&As[k][ty * 4];
            float4 b = *(float4*)&Bs[k][tx * 4];
            float av[4] = {a.x, a.y, a.z, a.w};
            float bv[4] = {b.x, b.y, b.z, b.w};
            #pragma unroll
            for (int i = 0; i < 4; i++)
                #pragma unroll
                for (int j = 0; j < 4; j++) acc[i][j] += av[i] * bv[j];
        }
        __syncthreads();
    }
    float* simb = g_sim + (size_t)blockIdx.z * (NN * NN);
    #pragma unroll
    for (int i = 0; i < 4; i++) {
        int n0 = by * 32 + ty * 4 + i;
        if (n0 >= NN) break;
        int mcol = bx * 32 + tx * 4;
        if (mcol + 3 < NN) {
            *(float4*)(simb + n0 * NN + mcol) =
                make_float4(acc[i][0], acc[i][1], acc[i][2], acc[i][3]);
        } else {
            #pragma unroll
            for (int j = 0; j < 4; j++)
                if (mcol + j < NN) simb[n0 * NN + mcol + j] = acc[i][j];
        }
    }
}

// ---------------------------------------------------------------------------
// Kernel 5a: fp32 top-16 candidates per row (8-slot safety margin).
// ---------------------------------------------------------------------------
__global__ void cand_kernel() {
    int t = blockIdx.x * blockDim.x + threadIdx.x;
    if (t >= M_NODES) return;
    int b = t / NN, n = t % NN;
    const float* row = g_sim + (size_t)b * (NN * NN) + n * NN;
    float val[NC]; int idx[NC];
    #pragma unroll
    for (int i = 0; i < NC; i++) { val[i] = -1e30f; idx[i] = 0; }
    for (int m4 = 0; m4 < NN; m4 += 4) {
        float4 vv = *(const float4*)(row + m4);
        float vs[4] = {vv.x, vv.y, vv.z, vv.w};
        #pragma unroll
        for (int q = 0; q < 4; q++) {
            int m = m4 + q;
            if (m == n) continue;
            float v = vs[q];
            if (v > val[NC - 1]) {
                int i = NC - 1;
                while (i > 0 && v > val[i - 1]) {
                    val[i] = val[i - 1]; idx[i] = idx[i - 1]; i--;
                }
                val[i] = v; idx[i] = m;
            }
        }
    }
    #pragma unroll
    for (int k = 0; k < NC; k++) g_cand[t * NC + k] = idx[k];
}

// ---------------------------------------------------------------------------
// Kernel 5b: exact re-rank in double; fp32 round; stable sort; emit top-8.
// ---------------------------------------------------------------------------
__global__ void refine_kernel(const float* __restrict__ nodes, float* __restrict__ adj_out) {
    __shared__ float skey[8][NC];
    __shared__ int   sidx[8][NC];
    int wip = threadIdx.x >> 5;
    int lane = threadIdx.x & 31;
    int t = blockIdx.x * 8 + wip;
    if (t >= M_NODES) return;
    int b = t / NN;
    int rowbase = b * NN;
    double dinv_n = g_dinv[t];
    float4 av = ((const float4*)(nodes + (size_t)t * DD))[lane];
    int myc = (lane < NC) ? g_cand[t * NC + lane] : 0;
    #pragma unroll
    for (int c = 0; c < NC; c++) {
        int j = __shfl_sync(~0u, myc, c);
        float4 bv = ((const float4*)(nodes + (size_t)(rowbase + j) * DD))[lane];
        double p = (double)av.x * bv.x + (double)av.y * bv.y
                 + (double)av.z * bv.z + (double)av.w * bv.w;
        #pragma unroll
        for (int o = 16; o > 0; o >>= 1) p += __shfl_xor_sync(~0u, p, o);
        if (lane == c) {
            double sim = p * dinv_n * g_dinv[rowbase + j];
            skey[wip][c] = (float)sim;
            sidx[wip][c] = j;
        }
    }
    __syncwarp();
    if (lane == 0) {
        float kv[NC]; int ki[NC];
        #pragma unroll
        for (int i = 0; i < NC; i++) { kv[i] = skey[wip][i]; ki[i] = sidx[wip][i]; }
        #pragma unroll
        for (int i = 1; i < NC; i++) {
            float v = kv[i]; int id = ki[i];
            int p = i - 1;
            while (p >= 0 && (kv[p] < v || (kv[p] == v && ki[p] > id))) {
                kv[p + 1] = kv[p]; ki[p + 1] = ki[p]; p--;
            }
            kv[p + 1] = v; ki[p + 1] = id;
        }
        #pragma unroll
        for (int k = 0; k < TK; k++) {
            g_adj[t * TK + k] = ki[k];
            adj_out[t * TK + k] = (float)ki[k];
        }
    }
}

// ---------------------------------------------------------------------------
// Kernel 6: C{1,2} = nodes @ We1[seg*128 : seg*128+128].
// r3 edge2 skeleton: 64x128 tile, 256 threads, 8x4 micro, Kc=32.
// ---------------------------------------------------------------------------
__global__ void cgemm64_kernel(const float* __restrict__ nodes, const float* __restrict__ We1) {
    __shared__ float As[32][65];
    __shared__ float4 Bs[1024];
    int tid = threadIdx.x;
    int m0 = blockIdx.x * 64;
    int seg = blockIdx.y;
    float* C = seg ? g_c2 : g_c1;
    const float* W = We1 + (size_t)seg * 128 * DD;
    int tx = tid & 31, ty = tid >> 5;
    float acc[8][4] = {};
    for (int k0 = 0; k0 < 128; k0 += 32) {
        {
            int r = tid >> 2, cb = (tid & 3) * 8;
            const float4* p = (const float4*)(nodes + (size_t)(m0 + r) * DD + k0 + cb);
            float4 v0 = p[0], v1 = p[1];
            As[cb + 0][r] = v0.x; As[cb + 1][r] = v0.y; As[cb + 2][r] = v0.z; As[cb + 3][r] = v0.w;
            As[cb + 4][r] = v1.x; As[cb + 5][r] = v1.y; As[cb + 6][r] = v1.z; As[cb + 7][r] = v1.w;
        }
        {
            const float4* Wg = (const float4*)(W + k0 * DD);
            #pragma unroll
            for (int i = 0; i < 4; i++) Bs[tid + i * 256] = Wg[tid + i * 256];
        }
        __syncthreads();
        #pragma unroll
        for (int cc = 0; cc < 32; cc++) {
            float4 bv = Bs[cc * 32 + tx];
            #pragma unroll
            for (int i = 0; i < 8; i++) {
                float a = As[cc][ty + 8 * i];
                acc[i][0] += a * bv.x; acc[i][1] += a * bv.y;
                acc[i][2] += a * bv.z; acc[i][3] += a * bv.w;
            }
        }
        __syncthreads();
    }
    #pragma unroll
    for (int i = 0; i < 8; i++) {
        int row = m0 + ty + 8 * i;
        ((float4*)(C + (size_t)row * DD))[tx] =
            make_float4(acc[i][0], acc[i][1], acc[i][2], acc[i][3]);
    }
}

// ---------------------------------------------------------------------------
// Kernel 7: C3 = table @ We1[256:384] + be1 (729 rows, tiny).
// ---------------------------------------------------------------------------
__global__ void c3_kernel(const float* __restrict__ We1, const float* __restrict__ be1) {
    __shared__ float ts[128];
    int row = blockIdx.x, t = threadIdx.x;
    ts[t] = g_table[row * DD + t];
    __syncthreads();
    float acc = be1[t];
    const float* W = We1 + (size_t)256 * DD;
    #pragma unroll 8
    for (int k = 0; k < 128; k++) acc += ts[k] * W[k * DD + t];
    g_c3[row * DD + t] = acc;
}

// ---------------------------------------------------------------------------
// Kernel 8: edges = GELU(C1[n] + C2[adj] + C3[disp]) @ We2 + be2.
// r3 edge2 skeleton (64x128, 8x4 micro); A tile from 3-way gather + GELU.
// ---------------------------------------------------------------------------
__global__ void edge_fused64_kernel(const float* __restrict__ We2, const float* __restrict__ be2,
                                    float* __restrict__ edges_out) {
    __shared__ float As[32][65];
    __shared__ float4 Bs[1024];
    __shared__ int s1[64], s2[64], s3[64];
    int tid = threadIdx.x;
    int m0 = blockIdx.x * 64;
    if (tid < 64) {
        int e = m0 + tid;
        int bn = e >> 3;
        int b = bn / NN, n = bn - b * NN;
        int j = g_adj[e];
        s1[tid] = bn * DD;
        s2[tid] = (b * NN + j) * DD;
        int rn = n / 14, cn = n % 14, rj = j / 14, cj = j % 14;
        s3[tid] = ((rj - rn + 13) * 27 + (cj - cn + 13)) * DD;
    }
    __syncthreads();
    int tx = tid & 31, ty = tid >> 5;
    int gr = tid >> 2, gc = (tid & 3) * 8;     // gather: 4 threads per row, 8 floats each
    float acc[8][4] = {};
    for (int k0 = 0; k0 < 128; k0 += 32) {
        {
            const float* p1 = g_c1 + s1[gr] + k0 + gc;
            const float* p2 = g_c2 + s2[gr] + k0 + gc;
            const float* p3 = g_c3 + s3[gr] + k0 + gc;
            #pragma unroll
            for (int q = 0; q < 2; q++) {
                float4 v1 = *(const float4*)(p1 + q * 4);
                float4 v2 = *(const float4*)(p2 + q * 4);
                float4 v3 = *(const float4*)(p3 + q * 4);
                As[gc + q * 4 + 0][gr] = gelu_exact(v1.x + v2.x + v3.x);
                As[gc + q * 4 + 1][gr] = gelu_exact(v1.y + v2.y + v3.y);
                As[gc + q * 4 + 2][gr] = gelu_exact(v1.z + v2.z + v3.z);
                As[gc + q * 4 + 3][gr] = gelu_exact(v1.w + v2.w + v3.w);
            }
        }
        {
            const float4* Wg = (const float4*)(We2 + k0 * DD);
            #pragma unroll
            for (int i = 0; i < 4; i++) Bs[tid + i * 256] = Wg[tid + i * 256];
        }
        __syncthreads();
        #pragma unroll
        for (int cc = 0; cc < 32; cc++) {
            float4 bv = Bs[cc * 32 + tx];
            #pragma unroll
            for (int i = 0; i < 8; i++) {
                float a = As[cc][ty + 8 * i];
                acc[i][0] += a * bv.x; acc[i][1] += a * bv.y;
                acc[i][2] += a * bv.z; acc[i][3] += a * bv.w;
            }
        }
        __syncthreads();
    }
    float4 bb = ((const float4*)be2)[tx];
    #pragma unroll
    for (int i = 0; i < 8; i++) {
        int row = m0 + ty + 8 * i;
        ((float4*)(edges_out + (size_t)row * DD))[tx] =
            make_float4(acc[i][0] + bb.x, acc[i][1] + bb.y,
                        acc[i][2] + bb.z, acc[i][3] + bb.w);
    }
}

// ---------------------------------------------------------------------------
extern "C" void kernel_launch(void* const* d_in, const int* in_sizes, int n_in,
                              void* d_out, int out_size) {
    const float* feat = (const float*)d_in[0];
    const float* Wn   = (const float*)d_in[1];
    const float* bn   = (const float*)d_in[2];
    const float* lng  = (const float*)d_in[3];
    const float* lnb  = (const float*)d_in[4];
    const float* Wp1  = (const float*)d_in[5];
    const float* bp1  = (const float*)d_in[6];
    const float* Wp2  = (const float*)d_in[7];
    const float* bp2  = (const float*)d_in[8];
    const float* We1  = (const float*)d_in[9];
    const float* be1  = (const float*)d_in[10];
    const float* We2  = (const float*)d_in[11];
    const float* be2  = (const float*)d_in[12];

    float* out = (float*)d_out;
    float* nodes_out = out;                                   // B*N*D
    float* edges_out = out + (size_t)M_NODES * DD;            // B*N*K*D
    float* adj_out   = edges_out + (size_t)NE * DD;           // B*N*K

    pos_table_kernel<<<729, 128>>>(Wp1, bp1, Wp2, bp2);
    node_kernel<<<M_NODES / 64, 256>>>(feat, Wn, bn, lng, lnb, nodes_out);
    norm_kernel<<<(M_NODES * 32) / 256, 256>>>(nodes_out);
    sim_kernel<<<dim3(7, 7, BB), 64>>>();
    cand_kernel<<<(M_NODES + 255) / 256, 256>>>();
    refine_kernel<<<(M_NODES + 7) / 8, 256>>>(nodes_out, adj_out);
    cgemm64_kernel<<<dim3(M_NODES / 64, 2), 256>>>(nodes_out, We1);
    c3_kernel<<<729, 128>>>(We1, be1);
    edge_fused64_kernel<<<NE / 64, 256>>>(We2, be2, edges_out);
}

// round 8
// speedup vs baseline: 1.8150x; 1.1412x over previous
#include <cuda_runtime.h>
#include <math.h>

// Problem constants
#define BB 128
#define CC 768
#define NN 196
#define DD 128
#define TK 8
#define NC 16                      // candidate count for exact re-rank
#define M_NODES (BB * NN)          // 25088
#define NE      (M_NODES * TK)     // 200704

// Scratch (device globals; no allocations allowed)
__device__ float  g_nrm[M_NODES * DD];          // normalized nodes (fp32, candidate stage)
__device__ float  g_sim[BB * NN * NN];          // similarity (fp32, candidate stage)
__device__ double g_dinv[M_NODES];              // double 1/||node||
__device__ int    g_cand[M_NODES * NC];         // top-16 fp32 candidates
__device__ int    g_adj[NE];                    // final top-8 indices
__device__ float  g_table[27 * 27 * DD];        // pos-MLP table
__device__ float  g_c1[M_NODES * DD];           // nodes @ We1[0:128]
__device__ float  g_c2[M_NODES * DD];           // nodes @ We1[128:256]
__device__ float  g_c3[27 * 27 * DD];           // table @ We1[256:384] + be1

__device__ __forceinline__ float gelu_exact(float x) {
    return 0.5f * x * (1.0f + erff(x * 0.70710678118654752440f));
}
__device__ __forceinline__ double gelu_exact_d(double x) {
    return 0.5 * x * (1.0 + erf(x * 0.7071067811865475244));
}

// ---------------------------------------------------------------------------
// Kernel 1: pos-MLP table. disp has only 27x27 distinct values (i/13 grid).
// ---------------------------------------------------------------------------
__global__ void pos_table_kernel(const float* __restrict__ Wp1, const float* __restrict__ bp1,
                                 const float* __restrict__ Wp2, const float* __restrict__ bp2) {
    __shared__ float h[64];
    int idx = blockIdx.x;
    float dy = (float)(idx / 27 - 13) * (1.0f / 13.0f);
    float dx = (float)(idx % 27 - 13) * (1.0f / 13.0f);
    int t = threadIdx.x;
    if (t < 64) {
        float v = dy * Wp1[t] + dx * Wp1[64 + t] + bp1[t];
        h[t] = gelu_exact(v);
    }
    __syncthreads();
    float acc = bp2[t];
    #pragma unroll 8
    for (int i = 0; i < 64; i++) acc += h[i] * Wp2[i * DD + t];
    g_table[idx * DD + t] = acc;
}

// ---------------------------------------------------------------------------
// Kernel 2: nodes = GELU(LN(tokens @ W_node + b_node)).
// Chunked-double accumulation (48 k-elems per DADD). LN+GELU in double.
// Micro-tile rows contiguous per thread: A-fragment = 2 broadcast LDS.128.
// ---------------------------------------------------------------------------
__global__ void node_kernel(const float* __restrict__ feat, const float* __restrict__ Wn,
                            const float* __restrict__ bnode, const float* __restrict__ ln_g,
                            const float* __restrict__ ln_b, float* __restrict__ nodes_out) {
    __shared__ float As[16][68];
    __shared__ float4 Bs[16 * 32];
    __shared__ float Cs[64][128];
    __shared__ int s_base[64];
    int tid = threadIdx.x;
    int m0 = blockIdx.x * 64;
    if (tid < 64) {
        int m = m0 + tid;
        int b = m / NN, n = m % NN;
        s_base[tid] = b * (CC * NN) + n;
    }
    int tx = tid & 31, ty = tid >> 5;
    double dacc[8][4];
    #pragma unroll
    for (int i = 0; i < 8; i++)
        #pragma unroll
        for (int q = 0; q < 4; q++) dacc[i][q] = 0.0;
    float acc16[8][4];
    #pragma unroll
    for (int i = 0; i < 8; i++)
        #pragma unroll
        for (int q = 0; q < 4; q++) acc16[i][q] = 0.f;
    int cnt = 0;
    __syncthreads();
    for (int k0 = 0; k0 < CC; k0 += 16) {
        #pragma unroll
        for (int i = 0; i < 4; i++) {
            int e = tid + i * 256;
            int r = e & 63, cc = e >> 6;
            As[cc][r] = feat[s_base[r] + (k0 + cc) * NN];
        }
        const float4* Wg = (const float4*)(Wn + k0 * DD);
        Bs[tid] = Wg[tid];
        Bs[tid + 256] = Wg[tid + 256];
        __syncthreads();
        #pragma unroll
        for (int cc = 0; cc < 16; cc++) {
            float4 bv = Bs[cc * 32 + tx];
            float4 a0 = *(float4*)&As[cc][ty * 8];
            float4 a1 = *(float4*)&As[cc][ty * 8 + 4];
            float ar[8] = {a0.x, a0.y, a0.z, a0.w, a1.x, a1.y, a1.z, a1.w};
            #pragma unroll
            for (int i = 0; i < 8; i++) {
                acc16[i][0] += ar[i] * bv.x; acc16[i][1] += ar[i] * bv.y;
                acc16[i][2] += ar[i] * bv.z; acc16[i][3] += ar[i] * bv.w;
            }
        }
        if (++cnt == 3) {
            cnt = 0;
            #pragma unroll
            for (int i = 0; i < 8; i++)
                #pragma unroll
                for (int q = 0; q < 4; q++) {
                    dacc[i][q] += (double)acc16[i][q];
                    acc16[i][q] = 0.f;
                }
        }
        __syncthreads();
    }
    float4 bb = ((const float4*)bnode)[tx];
    #pragma unroll
    for (int i = 0; i < 8; i++) {
        int r = ty * 8 + i;
        Cs[r][tx * 4 + 0] = (float)(dacc[i][0] + (double)bb.x);
        Cs[r][tx * 4 + 1] = (float)(dacc[i][1] + (double)bb.y);
        Cs[r][tx * 4 + 2] = (float)(dacc[i][2] + (double)bb.z);
        Cs[r][tx * 4 + 3] = (float)(dacc[i][3] + (double)bb.w);
    }
    __syncthreads();
    // LayerNorm + GELU in double, one warp per row
    int lane = tx, w = ty;
    for (int rr = 0; rr < 8; rr++) {
        int r = w + 8 * rr;
        double x[4];
        double s = 0.0;
        #pragma unroll
        for (int q = 0; q < 4; q++) { x[q] = (double)Cs[r][lane + 32 * q]; s += x[q]; }
        #pragma unroll
        for (int o = 16; o > 0; o >>= 1) s += __shfl_xor_sync(~0u, s, o);
        double mu = s * (1.0 / 128.0);
        double vs = 0.0;
        #pragma unroll
        for (int q = 0; q < 4; q++) { double d = x[q] - mu; vs += d * d; }
        #pragma unroll
        for (int o = 16; o > 0; o >>= 1) vs += __shfl_xor_sync(~0u, vs, o);
        double rs = 1.0 / sqrt(vs * (1.0 / 128.0) + 1e-5);
        int row = m0 + r;
        #pragma unroll
        for (int q = 0; q < 4; q++) {
            int d = lane + 32 * q;
            double y = (x[q] - mu) * rs * (double)ln_g[d] + (double)ln_b[d];
            nodes_out[(size_t)row * DD + d] = (float)gelu_exact_d(y);
        }
    }
}

// ---------------------------------------------------------------------------
// Kernel 3: L2-normalize nodes (warp per row).
// ---------------------------------------------------------------------------
__global__ void norm_kernel(const float* __restrict__ nodes) {
    int w = (blockIdx.x * blockDim.x + threadIdx.x) >> 5;
    int lane = threadIdx.x & 31;
    if (w >= M_NODES) return;
    const float4* rp = (const float4*)(nodes + (size_t)w * DD);
    float4 v = rp[lane];
    double s = (double)v.x * v.x + (double)v.y * v.y + (double)v.z * v.z + (double)v.w * v.w;
    #pragma unroll
    for (int o = 16; o > 0; o >>= 1) s += __shfl_xor_sync(~0u, s, o);
    double dinv = 1.0 / fmax(sqrt(s), 1e-12);
    if (lane == 0) g_dinv[w] = dinv;
    float inv = (float)dinv;
    ((float4*)(g_nrm + (size_t)w * DD))[lane] =
        make_float4(v.x * inv, v.y * inv, v.z * inv, v.w * inv);
}

// ---------------------------------------------------------------------------
// Kernel 4: sim = nrm @ nrm^T per batch. 32x32 tile, 64 threads, 4x4 micro.
// ---------------------------------------------------------------------------
__global__ void sim_kernel() {
    __shared__ float As[32][36];
    __shared__ float Bs[32][36];
    int tid = threadIdx.x;
    const float* base = g_nrm + (size_t)blockIdx.z * (NN * DD);
    int by = blockIdx.y, bx = blockIdx.x;
    int tx = tid & 7, ty = tid >> 3;
    float acc[4][4] = {};
    for (int k0 = 0; k0 < 128; k0 += 32) {
        #pragma unroll
        for (int it = 0; it < 4; it++) {
            int idx = tid + it * 64;                 // 0..255
            int r = idx >> 3, kg = (idx & 7) * 4;
            int na = by * 32 + r;
            float4 v = (na < NN) ? *(const float4*)(base + (size_t)na * DD + k0 + kg)
                                 : make_float4(0.f, 0.f, 0.f, 0.f);
            As[kg + 0][r] = v.x; As[kg + 1][r] = v.y; As[kg + 2][r] = v.z; As[kg + 3][r] = v.w;
            int ma = bx * 32 + r;
            float4 u = (ma < NN) ? *(const float4*)(base + (size_t)ma * DD + k0 + kg)
                                 : make_float4(0.f, 0.f, 0.f, 0.f);
            Bs[kg + 0][r] = u.x; Bs[kg + 1][r] = u.y; Bs[kg + 2][r] = u.z; Bs[kg + 3][r] = u.w;
        }
        __syncthreads();
        #pragma unroll
        for (int k = 0; k < 32; k++) {
            float4 a = *(float4*)&As[k][ty * 4];
            float4 b = *(float4*)&Bs[k][tx * 4];
            float av[4] = {a.x, a.y, a.z, a.w};
            float bv[4] = {b.x, b.y, b.z, b.w};
            #pragma unroll
            for (int i = 0; i < 4; i++)
                #pragma unroll
                for (int j = 0; j < 4; j++) acc[i][j] += av[i] * bv[j];
        }
        __syncthreads();
    }
    float* simb = g_sim + (size_t)blockIdx.z * (NN * NN);
    #pragma unroll
    for (int i = 0; i < 4; i++) {
        int n0 = by * 32 + ty * 4 + i;
        if (n0 >= NN) break;
        int mcol = bx * 32 + tx * 4;
        if (mcol + 3 < NN) {
            *(float4*)(simb + n0 * NN + mcol) =
                make_float4(acc[i][0], acc[i][1], acc[i][2], acc[i][3]);
        } else {
            #pragma unroll
            for (int j = 0; j < 4; j++)
                if (mcol + j < NN) simb[n0 * NN + mcol + j] = acc[i][j];
        }
    }
}

// ---------------------------------------------------------------------------
// Kernel 5a: fp32 top-16 candidates per row (8-slot safety margin).
// ---------------------------------------------------------------------------
__global__ void cand_kernel() {
    int t = blockIdx.x * blockDim.x + threadIdx.x;
    if (t >= M_NODES) return;
    int b = t / NN, n = t % NN;
    const float* row = g_sim + (size_t)b * (NN * NN) + n * NN;
    float val[NC]; int idx[NC];
    #pragma unroll
    for (int i = 0; i < NC; i++) { val[i] = -1e30f; idx[i] = 0; }
    for (int m4 = 0; m4 < NN; m4 += 4) {
        float4 vv = *(const float4*)(row + m4);
        float vs[4] = {vv.x, vv.y, vv.z, vv.w};
        #pragma unroll
        for (int q = 0; q < 4; q++) {
            int m = m4 + q;
            if (m == n) continue;
            float v = vs[q];
            if (v > val[NC - 1]) {
                int i = NC - 1;
                while (i > 0 && v > val[i - 1]) {
                    val[i] = val[i - 1]; idx[i] = idx[i - 1]; i--;
                }
                val[i] = v; idx[i] = m;
            }
        }
    }
    #pragma unroll
    for (int k = 0; k < NC; k++) g_cand[t * NC + k] = idx[k];
}

// ---------------------------------------------------------------------------
// Kernel 5b: exact re-rank in double; fp32 round; stable sort; emit top-8.
// ---------------------------------------------------------------------------
__global__ void refine_kernel(const float* __restrict__ nodes, float* __restrict__ adj_out) {
    __shared__ float skey[8][NC];
    __shared__ int   sidx[8][NC];
    int wip = threadIdx.x >> 5;
    int lane = threadIdx.x & 31;
    int t = blockIdx.x * 8 + wip;
    if (t >= M_NODES) return;
    int b = t / NN;
    int rowbase = b * NN;
    double dinv_n = g_dinv[t];
    float4 av = ((const float4*)(nodes + (size_t)t * DD))[lane];
    int myc = (lane < NC) ? g_cand[t * NC + lane] : 0;
    #pragma unroll
    for (int c = 0; c < NC; c++) {
        int j = __shfl_sync(~0u, myc, c);
        float4 bv = ((const float4*)(nodes + (size_t)(rowbase + j) * DD))[lane];
        double p = (double)av.x * bv.x + (double)av.y * bv.y
                 + (double)av.z * bv.z + (double)av.w * bv.w;
        #pragma unroll
        for (int o = 16; o > 0; o >>= 1) p += __shfl_xor_sync(~0u, p, o);
        if (lane == c) {
            double sim = p * dinv_n * g_dinv[rowbase + j];
            skey[wip][c] = (float)sim;
            sidx[wip][c] = j;
        }
    }
    __syncwarp();
    if (lane == 0) {
        float kv[NC]; int ki[NC];
        #pragma unroll
        for (int i = 0; i < NC; i++) { kv[i] = skey[wip][i]; ki[i] = sidx[wip][i]; }
        #pragma unroll
        for (int i = 1; i < NC; i++) {
            float v = kv[i]; int id = ki[i];
            int p = i - 1;
            while (p >= 0 && (kv[p] < v || (kv[p] == v && ki[p] > id))) {
                kv[p + 1] = kv[p]; ki[p + 1] = ki[p]; p--;
            }
            kv[p + 1] = v; ki[p + 1] = id;
        }
        #pragma unroll
        for (int k = 0; k < TK; k++) {
            g_adj[t * TK + k] = ki[k];
            adj_out[t * TK + k] = (float)ki[k];
        }
    }
}

// ---------------------------------------------------------------------------
// Kernel 6: C{1,2} = nodes @ We1[seg*128 : seg*128+128].
// 64x128 tile, 256 threads, 8x4 micro with contiguous rows (2 LDS.128 for A).
// ---------------------------------------------------------------------------
__global__ void cgemm64_kernel(const float* __restrict__ nodes, const float* __restrict__ We1) {
    __shared__ float As[32][68];
    __shared__ float4 Bs[1024];
    int tid = threadIdx.x;
    int m0 = blockIdx.x * 64;
    int seg = blockIdx.y;
    float* C = seg ? g_c2 : g_c1;
    const float* W = We1 + (size_t)seg * 128 * DD;
    int tx = tid & 31, ty = tid >> 5;
    float acc[8][4] = {};
    for (int k0 = 0; k0 < 128; k0 += 32) {
        {
            int r = tid >> 2, cb = (tid & 3) * 8;
            const float4* p = (const float4*)(nodes + (size_t)(m0 + r) * DD + k0 + cb);
            float4 v0 = p[0], v1 = p[1];
            As[cb + 0][r] = v0.x; As[cb + 1][r] = v0.y; As[cb + 2][r] = v0.z; As[cb + 3][r] = v0.w;
            As[cb + 4][r] = v1.x; As[cb + 5][r] = v1.y; As[cb + 6][r] = v1.z; As[cb + 7][r] = v1.w;
        }
        {
            const float4* Wg = (const float4*)(W + k0 * DD);
            #pragma unroll
            for (int i = 0; i < 4; i++) Bs[tid + i * 256] = Wg[tid + i * 256];
        }
        __syncthreads();
        #pragma unroll
        for (int cc = 0; cc < 32; cc++) {
            float4 bv = Bs[cc * 32 + tx];
            float4 a0 = *(float4*)&As[cc][ty * 8];
            float4 a1 = *(float4*)&As[cc][ty * 8 + 4];
            float ar[8] = {a0.x, a0.y, a0.z, a0.w, a1.x, a1.y, a1.z, a1.w};
            #pragma unroll
            for (int i = 0; i < 8; i++) {
                acc[i][0] += ar[i] * bv.x; acc[i][1] += ar[i] * bv.y;
                acc[i][2] += ar[i] * bv.z; acc[i][3] += ar[i] * bv.w;
            }
        }
        __syncthreads();
    }
    #pragma unroll
    for (int i = 0; i < 8; i++) {
        int row = m0 + ty * 8 + i;
        ((float4*)(C + (size_t)row * DD))[tx] =
            make_float4(acc[i][0], acc[i][1], acc[i][2], acc[i][3]);
    }
}

// ---------------------------------------------------------------------------
// Kernel 7: C3 = table @ We1[256:384] + be1 (729 rows, tiny).
// ---------------------------------------------------------------------------
__global__ void c3_kernel(const float* __restrict__ We1, const float* __restrict__ be1) {
    __shared__ float ts[128];
    int row = blockIdx.x, t = threadIdx.x;
    ts[t] = g_table[row * DD + t];
    __syncthreads();
    float acc = be1[t];
    const float* W = We1 + (size_t)256 * DD;
    #pragma unroll 8
    for (int k = 0; k < 128; k++) acc += ts[k] * W[k * DD + t];
    g_c3[row * DD + t] = acc;
}

// ---------------------------------------------------------------------------
// Kernel 8: edges = GELU(C1[n] + C2[adj] + C3[disp]) @ We2 + be2.
// 64x128 tile, 8x4 micro with contiguous rows; A tile from 3-way gather+GELU.
// ---------------------------------------------------------------------------
__global__ void edge_fused64_kernel(const float* __restrict__ We2, const float* __restrict__ be2,
                                    float* __restrict__ edges_out) {
    __shared__ float As[32][68];
    __shared__ float4 Bs[1024];
    __shared__ int s1[64], s2[64], s3[64];
    int tid = threadIdx.x;
    int m0 = blockIdx.x * 64;
    if (tid < 64) {
        int e = m0 + tid;
        int bn = e >> 3;
        int b = bn / NN, n = bn - b * NN;
        int j = g_adj[e];
        s1[tid] = bn * DD;
        s2[tid] = (b * NN + j) * DD;
        int rn = n / 14, cn = n % 14, rj = j / 14, cj = j % 14;
        s3[tid] = ((rj - rn + 13) * 27 + (cj - cn + 13)) * DD;
    }
    __syncthreads();
    int tx = tid & 31, ty = tid >> 5;
    int gr = tid >> 2, gc = (tid & 3) * 8;     // gather: 4 threads per row, 8 floats each
    float acc[8][4] = {};
    for (int k0 = 0; k0 < 128; k0 += 32) {
        {
            const float* p1 = g_c1 + s1[gr] + k0 + gc;
            const float* p2 = g_c2 + s2[gr] + k0 + gc;
            const float* p3 = g_c3 + s3[gr] + k0 + gc;
            #pragma unroll
            for (int q = 0; q < 2; q++) {
                float4 v1 = *(const float4*)(p1 + q * 4);
                float4 v2 = *(const float4*)(p2 + q * 4);
                float4 v3 = *(const float4*)(p3 + q * 4);
                As[gc + q * 4 + 0][gr] = gelu_exact(v1.x + v2.x + v3.x);
                As[gc + q * 4 + 1][gr] = gelu_exact(v1.y + v2.y + v3.y);
                As[gc + q * 4 + 2][gr] = gelu_exact(v1.z + v2.z + v3.z);
                As[gc + q * 4 + 3][gr] = gelu_exact(v1.w + v2.w + v3.w);
            }
        }
        {
            const float4* Wg = (const float4*)(We2 + k0 * DD);
            #pragma unroll
            for (int i = 0; i < 4; i++) Bs[tid + i * 256] = Wg[tid + i * 256];
        }
        __syncthreads();
        #pragma unroll
        for (int cc = 0; cc < 32; cc++) {
            float4 bv = Bs[cc * 32 + tx];
            float4 a0 = *(float4*)&As[cc][ty * 8];
            float4 a1 = *(float4*)&As[cc][ty * 8 + 4];
            float ar[8] = {a0.x, a0.y, a0.z, a0.w, a1.x, a1.y, a1.z, a1.w};
            #pragma unroll
            for (int i = 0; i < 8; i++) {
                acc[i][0] += ar[i] * bv.x; acc[i][1] += ar[i] * bv.y;
                acc[i][2] += ar[i] * bv.z; acc[i][3] += ar[i] * bv.w;
            }
        }
        __syncthreads();
    }
    float4 bb = ((const float4*)be2)[tx];
    #pragma unroll
    for (int i = 0; i < 8; i++) {
        int row = m0 + ty * 8 + i;
        ((float4*)(edges_out + (size_t)row * DD))[tx] =
            make_float4(acc[i][0] + bb.x, acc[i][1] + bb.y,
                        acc[i][2] + bb.z, acc[i][3] + bb.w);
    }
}

// ---------------------------------------------------------------------------
extern "C" void kernel_launch(void* const* d_in, const int* in_sizes, int n_in,
                              void* d_out, int out_size) {
    const float* feat = (const float*)d_in[0];
    const float* Wn   = (const float*)d_in[1];
    const float* bn   = (const float*)d_in[2];
    const float* lng  = (const float*)d_in[3];
    const float* lnb  = (const float*)d_in[4];
    const float* Wp1  = (const float*)d_in[5];
    const float* bp1  = (const float*)d_in[6];
    const float* Wp2  = (const float*)d_in[7];
    const float* bp2  = (const float*)d_in[8];
    const float* We1  = (const float*)d_in[9];
    const float* be1  = (const float*)d_in[10];
    const float* We2  = (const float*)d_in[11];
    const float* be2  = (const float*)d_in[12];

    float* out = (float*)d_out;
    float* nodes_out = out;                                   // B*N*D
    float* edges_out = out + (size_t)M_NODES * DD;            // B*N*K*D
    float* adj_out   = edges_out + (size_t)NE * DD;           // B*N*K

    pos_table_kernel<<<729, 128>>>(Wp1, bp1, Wp2, bp2);
    node_kernel<<<M_NODES / 64, 256>>>(feat, Wn, bn, lng, lnb, nodes_out);
    norm_kernel<<<(M_NODES * 32) / 256, 256>>>(nodes_out);
    sim_kernel<<<dim3(7, 7, BB), 64>>>();
    cand_kernel<<<(M_NODES + 255) / 256, 256>>>();
    refine_kernel<<<(M_NODES + 7) / 8, 256>>>(nodes_out, adj_out);
    cgemm64_kernel<<<dim3(M_NODES / 64, 2), 256>>>(nodes_out, We1);
    c3_kernel<<<729, 128>>>(We1, be1);
    edge_fused64_kernel<<<NE / 64, 256>>>(We2, be2, edges_out);
}

// round 9
// speedup vs baseline: 1.8311x; 1.0089x over previous
#include <cuda_runtime.h>
#include <math.h>

// Problem constants
#define BB 128
#define CC 768
#define NN 196
#define DD 128
#define TK 8
#define NC 16                      // candidate count for exact re-rank
#define M_NODES (BB * NN)          // 25088
#define NE      (M_NODES * TK)     // 200704

typedef unsigned long long u64;

// Scratch (device globals; no allocations allowed)
__device__ float  g_nrm[M_NODES * DD];          // normalized nodes (fp32, candidate stage)
__device__ float  g_sim[BB * NN * NN];          // similarity (fp32, candidate stage)
__device__ double g_dinv[M_NODES];              // double 1/||node||
__device__ int    g_cand[M_NODES * NC];         // top-16 fp32 candidates
__device__ int    g_adj[NE];                    // final top-8 indices
__device__ float  g_table[27 * 27 * DD];        // pos-MLP table
__device__ float  g_c1[M_NODES * DD];           // nodes @ We1[0:128]
__device__ float  g_c2[M_NODES * DD];           // nodes @ We1[128:256]
__device__ float  g_c3[27 * 27 * DD];           // table @ We1[256:384] + be1

__device__ __forceinline__ float gelu_exact(float x) {
    return 0.5f * x * (1.0f + erff(x * 0.70710678118654752440f));
}
__device__ __forceinline__ double gelu_exact_d(double x) {
    return 0.5 * x * (1.0 + erf(x * 0.7071067811865475244));
}

// ---- packed f32x2 helpers (sm_100+). IEEE fp32 per lane: bit-identical to
// scalar FFMA, so results match the scalar version exactly. ----
__device__ __forceinline__ u64 pack2(float x) {
    unsigned int u = __float_as_uint(x);
    u64 r;
    asm("mov.b64 %0, {%1, %1};" : "=l"(r) : "r"(u));
    return r;
}
__device__ __forceinline__ void fma2(u64& d, u64 a, u64 b) {
    asm("fma.rn.f32x2 %0, %1, %2, %0;" : "+l"(d) : "l"(a), "l"(b));
}
__device__ __forceinline__ float2 unpack2(u64 v) {
    unsigned int lo, hi;
    asm("mov.b64 {%0, %1}, %2;" : "=r"(lo), "=r"(hi) : "l"(v));
    return make_float2(__uint_as_float(lo), __uint_as_float(hi));
}

// ---------------------------------------------------------------------------
// Kernel 1: pos-MLP table. disp has only 27x27 distinct values (i/13 grid).
// ---------------------------------------------------------------------------
__global__ void pos_table_kernel(const float* __restrict__ Wp1, const float* __restrict__ bp1,
                                 const float* __restrict__ Wp2, const float* __restrict__ bp2) {
    __shared__ float h[64];
    int idx = blockIdx.x;
    float dy = (float)(idx / 27 - 13) * (1.0f / 13.0f);
    float dx = (float)(idx % 27 - 13) * (1.0f / 13.0f);
    int t = threadIdx.x;
    if (t < 64) {
        float v = dy * Wp1[t] + dx * Wp1[64 + t] + bp1[t];
        h[t] = gelu_exact(v);
    }
    __syncthreads();
    float acc = bp2[t];
    #pragma unroll 8
    for (int i = 0; i < 64; i++) acc += h[i] * Wp2[i * DD + t];
    g_table[idx * DD + t] = acc;
}

// ---------------------------------------------------------------------------
// Kernel 2: nodes = GELU(LN(tokens @ W_node + b_node)).
// f32x2 packed FMA inner loop; chunked-double accumulation (48 k per DADD);
// LN+GELU in double. Row pairs packed in u64 accumulators.
// ---------------------------------------------------------------------------
__global__ void node_kernel(const float* __restrict__ feat, const float* __restrict__ Wn,
                            const float* __restrict__ bnode, const float* __restrict__ ln_g,
                            const float* __restrict__ ln_b, float* __restrict__ nodes_out) {
    __shared__ float As[16][68];
    __shared__ float4 Bs[16 * 32];
    __shared__ float Cs[64][128];
    __shared__ int s_base[64];
    int tid = threadIdx.x;
    int m0 = blockIdx.x * 64;
    if (tid < 64) {
        int m = m0 + tid;
        int b = m / NN, n = m % NN;
        s_base[tid] = b * (CC * NN) + n;
    }
    int tx = tid & 31, ty = tid >> 5;
    double dacc[8][4];
    #pragma unroll
    for (int i = 0; i < 8; i++)
        #pragma unroll
        for (int q = 0; q < 4; q++) dacc[i][q] = 0.0;
    u64 acc2[4][4] = {};                       // rowpair p = rows (2p,2p+1), col q
    int cnt = 0;
    __syncthreads();
    for (int k0 = 0; k0 < CC; k0 += 16) {
        #pragma unroll
        for (int i = 0; i < 4; i++) {
            int e = tid + i * 256;
            int r = e & 63, cc = e >> 6;
            As[cc][r] = feat[s_base[r] + (k0 + cc) * NN];
        }
        const float4* Wg = (const float4*)(Wn + k0 * DD);
        Bs[tid] = Wg[tid];
        Bs[tid + 256] = Wg[tid + 256];
        __syncthreads();
        #pragma unroll
        for (int cc = 0; cc < 16; cc++) {
            float4 bv = Bs[cc * 32 + tx];
            u64 b2[4] = {pack2(bv.x), pack2(bv.y), pack2(bv.z), pack2(bv.w)};
            ulonglong2 A01 = *(const ulonglong2*)&As[cc][ty * 8];
            ulonglong2 A23 = *(const ulonglong2*)&As[cc][ty * 8 + 4];
            u64 ap[4] = {A01.x, A01.y, A23.x, A23.y};
            #pragma unroll
            for (int p = 0; p < 4; p++)
                #pragma unroll
                for (int q = 0; q < 4; q++) fma2(acc2[p][q], ap[p], b2[q]);
        }
        if (++cnt == 3) {
            cnt = 0;
            #pragma unroll
            for (int p = 0; p < 4; p++)
                #pragma unroll
                for (int q = 0; q < 4; q++) {
                    float2 v = unpack2(acc2[p][q]);
                    dacc[2 * p][q]     += (double)v.x;
                    dacc[2 * p + 1][q] += (double)v.y;
                    acc2[p][q] = 0ull;
                }
        }
        __syncthreads();
    }
    float4 bb = ((const float4*)bnode)[tx];
    #pragma unroll
    for (int i = 0; i < 8; i++) {
        int r = ty * 8 + i;
        Cs[r][tx * 4 + 0] = (float)(dacc[i][0] + (double)bb.x);
        Cs[r][tx * 4 + 1] = (float)(dacc[i][1] + (double)bb.y);
        Cs[r][tx * 4 + 2] = (float)(dacc[i][2] + (double)bb.z);
        Cs[r][tx * 4 + 3] = (float)(dacc[i][3] + (double)bb.w);
    }
    __syncthreads();
    // LayerNorm + GELU in double, one warp per row
    int lane = tx, w = ty;
    for (int rr = 0; rr < 8; rr++) {
        int r = w + 8 * rr;
        double x[4];
        double s = 0.0;
        #pragma unroll
        for (int q = 0; q < 4; q++) { x[q] = (double)Cs[r][lane + 32 * q]; s += x[q]; }
        #pragma unroll
        for (int o = 16; o > 0; o >>= 1) s += __shfl_xor_sync(~0u, s, o);
        double mu = s * (1.0 / 128.0);
        double vs = 0.0;
        #pragma unroll
        for (int q = 0; q < 4; q++) { double d = x[q] - mu; vs += d * d; }
        #pragma unroll
        for (int o = 16; o > 0; o >>= 1) vs += __shfl_xor_sync(~0u, vs, o);
        double rs = 1.0 / sqrt(vs * (1.0 / 128.0) + 1e-5);
        int row = m0 + r;
        #pragma unroll
        for (int q = 0; q < 4; q++) {
            int d = lane + 32 * q;
            double y = (x[q] - mu) * rs * (double)ln_g[d] + (double)ln_b[d];
            nodes_out[(size_t)row * DD + d] = (float)gelu_exact_d(y);
        }
    }
}

// ---------------------------------------------------------------------------
// Kernel 3: L2-normalize nodes (warp per row).
// ---------------------------------------------------------------------------
__global__ void norm_kernel(const float* __restrict__ nodes) {
    int w = (blockIdx.x * blockDim.x + threadIdx.x) >> 5;
    int lane = threadIdx.x & 31;
    if (w >= M_NODES) return;
    const float4* rp = (const float4*)(nodes + (size_t)w * DD);
    float4 v = rp[lane];
    double s = (double)v.x * v.x + (double)v.y * v.y + (double)v.z * v.z + (double)v.w * v.w;
    #pragma unroll
    for (int o = 16; o > 0; o >>= 1) s += __shfl_xor_sync(~0u, s, o);
    double dinv = 1.0 / fmax(sqrt(s), 1e-12);
    if (lane == 0) g_dinv[w] = dinv;
    float inv = (float)dinv;
    ((float4*)(g_nrm + (size_t)w * DD))[lane] =
        make_float4(v.x * inv, v.y * inv, v.z * inv, v.w * inv);
}

// ---------------------------------------------------------------------------
// Kernel 4: sim = nrm @ nrm^T per batch. 32x32 tile, 64 threads, 4x4 micro,
// f32x2 packed FMA (rowpairs free from the float4 A fragment).
// ---------------------------------------------------------------------------
__global__ void sim_kernel() {
    __shared__ float As[32][36];
    __shared__ float Bs[32][36];
    int tid = threadIdx.x;
    const float* base = g_nrm + (size_t)blockIdx.z * (NN * DD);
    int by = blockIdx.y, bx = blockIdx.x;
    int tx = tid & 7, ty = tid >> 3;
    u64 acc2[2][4] = {};                       // rowpair p = rows (2p,2p+1), col j
    for (int k0 = 0; k0 < 128; k0 += 32) {
        #pragma unroll
        for (int it = 0; it < 4; it++) {
            int idx = tid + it * 64;                 // 0..255
            int r = idx >> 3, kg = (idx & 7) * 4;
            int na = by * 32 + r;
            float4 v = (na < NN) ? *(const float4*)(base + (size_t)na * DD + k0 + kg)
                                 : make_float4(0.f, 0.f, 0.f, 0.f);
            As[kg + 0][r] = v.x; As[kg + 1][r] = v.y; As[kg + 2][r] = v.z; As[kg + 3][r] = v.w;
            int ma = bx * 32 + r;
            float4 u = (ma < NN) ? *(const float4*)(base + (size_t)ma * DD + k0 + kg)
                                 : make_float4(0.f, 0.f, 0.f, 0.f);
            Bs[kg + 0][r] = u.x; Bs[kg + 1][r] = u.y; Bs[kg + 2][r] = u.z; Bs[kg + 3][r] = u.w;
        }
        __syncthreads();
        #pragma unroll
        for (int k = 0; k < 32; k++) {
            ulonglong2 av = *(const ulonglong2*)&As[k][ty * 4];
            u64 ap[2] = {av.x, av.y};
            float4 b = *(float4*)&Bs[k][tx * 4];
            u64 b2[4] = {pack2(b.x), pack2(b.y), pack2(b.z), pack2(b.w)};
            #pragma unroll
            for (int p = 0; p < 2; p++)
                #pragma unroll
                for (int j = 0; j < 4; j++) fma2(acc2[p][j], ap[p], b2[j]);
        }
        __syncthreads();
    }
    float accf[4][4];
    #pragma unroll
    for (int p = 0; p < 2; p++)
        #pragma unroll
        for (int j = 0; j < 4; j++) {
            float2 v = unpack2(acc2[p][j]);
            accf[2 * p][j] = v.x;
            accf[2 * p + 1][j] = v.y;
        }
    float* simb = g_sim + (size_t)blockIdx.z * (NN * NN);
    #pragma unroll
    for (int i = 0; i < 4; i++) {
        int n0 = by * 32 + ty * 4 + i;
        if (n0 >= NN) break;
        int mcol = bx * 32 + tx * 4;
        if (mcol + 3 < NN) {
            *(float4*)(simb + n0 * NN + mcol) =
                make_float4(accf[i][0], accf[i][1], accf[i][2], accf[i][3]);
        } else {
            #pragma unroll
            for (int j = 0; j < 4; j++)
                if (mcol + j < NN) simb[n0 * NN + mcol + j] = accf[i][j];
        }
    }
}

// ---------------------------------------------------------------------------
// Kernel 5a: fp32 top-16 candidates per row (8-slot safety margin).
// ---------------------------------------------------------------------------
__global__ void cand_kernel() {
    int t = blockIdx.x * blockDim.x + threadIdx.x;
    if (t >= M_NODES) return;
    int b = t / NN, n = t % NN;
    const float* row = g_sim + (size_t)b * (NN * NN) + n * NN;
    float val[NC]; int idx[NC];
    #pragma unroll
    for (int i = 0; i < NC; i++) { val[i] = -1e30f; idx[i] = 0; }
    for (int m4 = 0; m4 < NN; m4 += 4) {
        float4 vv = *(const float4*)(row + m4);
        float vs[4] = {vv.x, vv.y, vv.z, vv.w};
        #pragma unroll
        for (int q = 0; q < 4; q++) {
            int m = m4 + q;
            if (m == n) continue;
            float v = vs[q];
            if (v > val[NC - 1]) {
                int i = NC - 1;
                while (i > 0 && v > val[i - 1]) {
                    val[i] = val[i - 1]; idx[i] = idx[i - 1]; i--;
                }
                val[i] = v; idx[i] = m;
            }
        }
    }
    #pragma unroll
    for (int k = 0; k < NC; k++) g_cand[t * NC + k] = idx[k];
}

// ---------------------------------------------------------------------------
// Kernel 5b: exact re-rank in double; fp32 round; stable sort; emit top-8.
// ---------------------------------------------------------------------------
__global__ void refine_kernel(const float* __restrict__ nodes, float* __restrict__ adj_out) {
    __shared__ float skey[8][NC];
    __shared__ int   sidx[8][NC];
    int wip = threadIdx.x >> 5;
    int lane = threadIdx.x & 31;
    int t = blockIdx.x * 8 + wip;
    if (t >= M_NODES) return;
    int b = t / NN;
    int rowbase = b * NN;
    double dinv_n = g_dinv[t];
    float4 av = ((const float4*)(nodes + (size_t)t * DD))[lane];
    int myc = (lane < NC) ? g_cand[t * NC + lane] : 0;
    #pragma unroll
    for (int c = 0; c < NC; c++) {
        int j = __shfl_sync(~0u, myc, c);
        float4 bv = ((const float4*)(nodes + (size_t)(rowbase + j) * DD))[lane];
        double p = (double)av.x * bv.x + (double)av.y * bv.y
                 + (double)av.z * bv.z + (double)av.w * bv.w;
        #pragma unroll
        for (int o = 16; o > 0; o >>= 1) p += __shfl_xor_sync(~0u, p, o);
        if (lane == c) {
            double sim = p * dinv_n * g_dinv[rowbase + j];
            skey[wip][c] = (float)sim;
            sidx[wip][c] = j;
        }
    }
    __syncwarp();
    if (lane == 0) {
        float kv[NC]; int ki[NC];
        #pragma unroll
        for (int i = 0; i < NC; i++) { kv[i] = skey[wip][i]; ki[i] = sidx[wip][i]; }
        #pragma unroll
        for (int i = 1; i < NC; i++) {
            float v = kv[i]; int id = ki[i];
            int p = i - 1;
            while (p >= 0 && (kv[p] < v || (kv[p] == v && ki[p] > id))) {
                kv[p + 1] = kv[p]; ki[p + 1] = ki[p]; p--;
            }
            kv[p + 1] = v; ki[p + 1] = id;
        }
        #pragma unroll
        for (int k = 0; k < TK; k++) {
            g_adj[t * TK + k] = ki[k];
            adj_out[t * TK + k] = (float)ki[k];
        }
    }
}

// ---------------------------------------------------------------------------
// Kernel 6: C{1,2} = nodes @ We1[seg*128 : seg*128+128].
// 64x128 tile, 256 threads, 8x4 micro, f32x2 packed FMA.
// ---------------------------------------------------------------------------
__global__ void cgemm64_kernel(const float* __restrict__ nodes, const float* __restrict__ We1) {
    __shared__ float As[32][68];
    __shared__ float4 Bs[1024];
    int tid = threadIdx.x;
    int m0 = blockIdx.x * 64;
    int seg = blockIdx.y;
    float* C = seg ? g_c2 : g_c1;
    const float* W = We1 + (size_t)seg * 128 * DD;
    int tx = tid & 31, ty = tid >> 5;
    u64 acc2[4][4] = {};
    for (int k0 = 0; k0 < 128; k0 += 32) {
        {
            int r = tid >> 2, cb = (tid & 3) * 8;
            const float4* p = (const float4*)(nodes + (size_t)(m0 + r) * DD + k0 + cb);
            float4 v0 = p[0], v1 = p[1];
            As[cb + 0][r] = v0.x; As[cb + 1][r] = v0.y; As[cb + 2][r] = v0.z; As[cb + 3][r] = v0.w;
            As[cb + 4][r] = v1.x; As[cb + 5][r] = v1.y; As[cb + 6][r] = v1.z; As[cb + 7][r] = v1.w;
        }
        {
            const float4* Wg = (const float4*)(W + k0 * DD);
            #pragma unroll
            for (int i = 0; i < 4; i++) Bs[tid + i * 256] = Wg[tid + i * 256];
        }
        __syncthreads();
        #pragma unroll
        for (int cc = 0; cc < 32; cc++) {
            float4 bv = Bs[cc * 32 + tx];
            u64 b2[4] = {pack2(bv.x), pack2(bv.y), pack2(bv.z), pack2(bv.w)};
            ulonglong2 A01 = *(const ulonglong2*)&As[cc][ty * 8];
            ulonglong2 A23 = *(const ulonglong2*)&As[cc][ty * 8 + 4];
            u64 ap[4] = {A01.x, A01.y, A23.x, A23.y};
            #pragma unroll
            for (int p = 0; p < 4; p++)
                #pragma unroll
                for (int q = 0; q < 4; q++) fma2(acc2[p][q], ap[p], b2[q]);
        }
        __syncthreads();
    }
    #pragma unroll
    for (int p = 0; p < 4; p++) {
        float2 v0 = unpack2(acc2[p][0]);
        float2 v1 = unpack2(acc2[p][1]);
        float2 v2 = unpack2(acc2[p][2]);
        float2 v3 = unpack2(acc2[p][3]);
        int row0 = m0 + ty * 8 + 2 * p;
        ((float4*)(C + (size_t)row0 * DD))[tx] = make_float4(v0.x, v1.x, v2.x, v3.x);
        ((float4*)(C + (size_t)(row0 + 1) * DD))[tx] = make_float4(v0.y, v1.y, v2.y, v3.y);
    }
}

// ---------------------------------------------------------------------------
// Kernel 7: C3 = table @ We1[256:384] + be1 (729 rows, tiny).
// ---------------------------------------------------------------------------
__global__ void c3_kernel(const float* __restrict__ We1, const float* __restrict__ be1) {
    __shared__ float ts[128];
    int row = blockIdx.x, t = threadIdx.x;
    ts[t] = g_table[row * DD + t];
    __syncthreads();
    float acc = be1[t];
    const float* W = We1 + (size_t)256 * DD;
    #pragma unroll 8
    for (int k = 0; k < 128; k++) acc += ts[k] * W[k * DD + t];
    g_c3[row * DD + t] = acc;
}

// ---------------------------------------------------------------------------
// Kernel 8: edges = GELU(C1[n] + C2[adj] + C3[disp]) @ We2 + be2.
// 64x128 tile, 8x4 micro, f32x2 packed FMA; A tile from 3-way gather + GELU.
// ---------------------------------------------------------------------------
__global__ void edge_fused64_kernel(const float* __restrict__ We2, const float* __restrict__ be2,
                                    float* __restrict__ edges_out) {
    __shared__ float As[32][68];
    __shared__ float4 Bs[1024];
    __shared__ int s1[64], s2[64], s3[64];
    int tid = threadIdx.x;
    int m0 = blockIdx.x * 64;
    if (tid < 64) {
        int e = m0 + tid;
        int bn = e >> 3;
        int b = bn / NN, n = bn - b * NN;
        int j = g_adj[e];
        s1[tid] = bn * DD;
        s2[tid] = (b * NN + j) * DD;
        int rn = n / 14, cn = n % 14, rj = j / 14, cj = j % 14;
        s3[tid] = ((rj - rn + 13) * 27 + (cj - cn + 13)) * DD;
    }
    __syncthreads();
    int tx = tid & 31, ty = tid >> 5;
    int gr = tid >> 2, gc = (tid & 3) * 8;     // gather: 4 threads per row, 8 floats each
    u64 acc2[4][4] = {};
    for (int k0 = 0; k0 < 128; k0 += 32) {
        {
            const float* p1 = g_c1 + s1[gr] + k0 + gc;
            const float* p2 = g_c2 + s2[gr] + k0 + gc;
            const float* p3 = g_c3 + s3[gr] + k0 + gc;
            #pragma unroll
            for (int q = 0; q < 2; q++) {
                float4 v1 = *(const float4*)(p1 + q * 4);
                float4 v2 = *(const float4*)(p2 + q * 4);
                float4 v3 = *(const float4*)(p3 + q * 4);
                As[gc + q * 4 + 0][gr] = gelu_exact(v1.x + v2.x + v3.x);
                As[gc + q * 4 + 1][gr] = gelu_exact(v1.y + v2.y + v3.y);
                As[gc + q * 4 + 2][gr] = gelu_exact(v1.z + v2.z + v3.z);
                As[gc + q * 4 + 3][gr] = gelu_exact(v1.w + v2.w + v3.w);
            }
        }
        {
            const float4* Wg = (const float4*)(We2 + k0 * DD);
            #pragma unroll
            for (int i = 0; i < 4; i++) Bs[tid + i * 256] = Wg[tid + i * 256];
        }
        __syncthreads();
        #pragma unroll
        for (int cc = 0; cc < 32; cc++) {
            float4 bv = Bs[cc * 32 + tx];
            u64 b2[4] = {pack2(bv.x), pack2(bv.y), pack2(bv.z), pack2(bv.w)};
            ulonglong2 A01 = *(const ulonglong2*)&As[cc][ty * 8];
            ulonglong2 A23 = *(const ulonglong2*)&As[cc][ty * 8 + 4];
            u64 ap[4] = {A01.x, A01.y, A23.x, A23.y};
            #pragma unroll
            for (int p = 0; p < 4; p++)
                #pragma unroll
                for (int q = 0; q < 4; q++) fma2(acc2[p][q], ap[p], b2[q]);
        }
        __syncthreads();
    }
    float4 bb = ((const float4*)be2)[tx];
    #pragma unroll
    for (int p = 0; p < 4; p++) {
        float2 v0 = unpack2(acc2[p][0]);
        float2 v1 = unpack2(acc2[p][1]);
        float2 v2 = unpack2(acc2[p][2]);
        float2 v3 = unpack2(acc2[p][3]);
        int row0 = m0 + ty * 8 + 2 * p;
        ((float4*)(edges_out + (size_t)row0 * DD))[tx] =
            make_float4(v0.x + bb.x, v1.x + bb.y, v2.x + bb.z, v3.x + bb.w);
        ((float4*)(edges_out + (size_t)(row0 + 1) * DD))[tx] =
            make_float4(v0.y + bb.x, v1.y + bb.y, v2.y + bb.z, v3.y + bb.w);
    }
}

// ---------------------------------------------------------------------------
extern "C" void kernel_launch(void* const* d_in, const int* in_sizes, int n_in,
                              void* d_out, int out_size) {
    const float* feat = (const float*)d_in[0];
    const float* Wn   = (const float*)d_in[1];
    const float* bn   = (const float*)d_in[2];
    const float* lng  = (const float*)d_in[3];
    const float* lnb  = (const float*)d_in[4];
    const float* Wp1  = (const float*)d_in[5];
    const float* bp1  = (const float*)d_in[6];
    const float* Wp2  = (const float*)d_in[7];
    const float* bp2  = (const float*)d_in[8];
    const float* We1  = (const float*)d_in[9];
    const float* be1  = (const float*)d_in[10];
    const float* We2  = (const float*)d_in[11];
    const float* be2  = (const float*)d_in[12];

    float* out = (float*)d_out;
    float* nodes_out = out;                                   // B*N*D
    float* edges_out = out + (size_t)M_NODES * DD;            // B*N*K*D
    float* adj_out   = edges_out + (size_t)NE * DD;           // B*N*K

    pos_table_kernel<<<729, 128>>>(Wp1, bp1, Wp2, bp2);
    node_kernel<<<M_NODES / 64, 256>>>(feat, Wn, bn, lng, lnb, nodes_out);
    norm_kernel<<<(M_NODES * 32) / 256, 256>>>(nodes_out);
    sim_kernel<<<dim3(7, 7, BB), 64>>>();
    cand_kernel<<<(M_NODES + 255) / 256, 256>>>();
    refine_kernel<<<(M_NODES + 7) / 8, 256>>>(nodes_out, adj_out);
    cgemm64_kernel<<<dim3(M_NODES / 64, 2), 256>>>(nodes_out, We1);
    c3_kernel<<<729, 128>>>(We1, be1);
    edge_fused64_kernel<<<NE / 64, 256>>>(We2, be2, edges_out);
}

// round 10
// speedup vs baseline: 1.8634x; 1.0177x over previous
#include <cuda_runtime.h>
#include <math.h>

// Problem constants
#define BB 128
#define CC 768
#define NN 196
#define DD 128
#define TK 8
#define NC 16                      // candidate count for exact re-rank
#define M_NODES (BB * NN)          // 25088
#define NE      (M_NODES * TK)     // 200704

typedef unsigned long long u64;

// Scratch (device globals; no allocations allowed)
__device__ float  g_nrm[M_NODES * DD];          // normalized nodes (fp32, candidate stage)
__device__ float  g_sim[BB * NN * NN];          // similarity (fp32, candidate stage)
__device__ double g_dinv[M_NODES];              // double 1/||node||
__device__ int    g_cand[M_NODES * NC];         // top-16 fp32 candidates
__device__ int    g_adj[NE];                    // final top-8 indices
__device__ float  g_table[27 * 27 * DD];        // pos-MLP table
__device__ float  g_c1[M_NODES * DD];           // nodes @ We1[0:128]
__device__ float  g_c2[M_NODES * DD];           // nodes @ We1[128:256]
__device__ float  g_c3[27 * 27 * DD];           // table @ We1[256:384] + be1

__device__ __forceinline__ float gelu_exact(float x) {
    return 0.5f * x * (1.0f + erff(x * 0.70710678118654752440f));
}
__device__ __forceinline__ double gelu_exact_d(double x) {
    return 0.5 * x * (1.0 + erf(x * 0.7071067811865475244));
}

// ---- packed f32x2 helpers (used by sim kernel; IEEE per-lane) ----
__device__ __forceinline__ u64 pack2(float x) {
    unsigned int u = __float_as_uint(x);
    u64 r;
    asm("mov.b64 %0, {%1, %1};" : "=l"(r) : "r"(u));
    return r;
}
__device__ __forceinline__ void fma2(u64& d, u64 a, u64 b) {
    asm("fma.rn.f32x2 %0, %1, %2, %0;" : "+l"(d) : "l"(a), "l"(b));
}
__device__ __forceinline__ float2 unpack2(u64 v) {
    unsigned int lo, hi;
    asm("mov.b64 {%0, %1}, %2;" : "=r"(lo), "=r"(hi) : "l"(v));
    return make_float2(__uint_as_float(lo), __uint_as_float(hi));
}

// ---------------------------------------------------------------------------
// Kernel 1: pos-MLP table. disp has only 27x27 distinct values (i/13 grid).
// ---------------------------------------------------------------------------
__global__ void pos_table_kernel(const float* __restrict__ Wp1, const float* __restrict__ bp1,
                                 const float* __restrict__ Wp2, const float* __restrict__ bp2) {
    __shared__ float h[64];
    int idx = blockIdx.x;
    float dy = (float)(idx / 27 - 13) * (1.0f / 13.0f);
    float dx = (float)(idx % 27 - 13) * (1.0f / 13.0f);
    int t = threadIdx.x;
    if (t < 64) {
        float v = dy * Wp1[t] + dx * Wp1[64 + t] + bp1[t];
        h[t] = gelu_exact(v);
    }
    __syncthreads();
    float acc = bp2[t];
    #pragma unroll 8
    for (int i = 0; i < 64; i++) acc += h[i] * Wp2[i * DD + t];
    g_table[idx * DD + t] = acc;
}

// ---------------------------------------------------------------------------
// Kernel 2: nodes = GELU(LN(tokens @ W_node + b_node)), fused L2-normalize.
// 32-row tile, 256 threads, 4x4 micro (low regs -> 3 blocks/SM).
// Chunked-double accumulation (48 k per DADD); LN+GELU in double.
// Writes nodes_out, g_nrm, g_dinv.
// ---------------------------------------------------------------------------
__global__ void node_kernel(const float* __restrict__ feat, const float* __restrict__ Wn,
                            const float* __restrict__ bnode, const float* __restrict__ ln_g,
                            const float* __restrict__ ln_b, float* __restrict__ nodes_out) {
    __shared__ float As[16][36];
    __shared__ float4 Bs[16 * 32];
    __shared__ float Cs[32][132];
    __shared__ int s_base[32];
    int tid = threadIdx.x;
    int m0 = blockIdx.x * 32;
    if (tid < 32) {
        int m = m0 + tid;
        int b = m / NN, n = m % NN;
        s_base[tid] = b * (CC * NN) + n;
    }
    int tx = tid & 31, ty = tid >> 5;
    double dacc[4][4];
    #pragma unroll
    for (int i = 0; i < 4; i++)
        #pragma unroll
        for (int q = 0; q < 4; q++) dacc[i][q] = 0.0;
    float acc[4][4] = {};
    int cnt = 0;
    __syncthreads();
    for (int k0 = 0; k0 < CC; k0 += 16) {
        #pragma unroll
        for (int i = 0; i < 2; i++) {
            int e = tid + i * 256;
            int r = e & 31, cc = e >> 5;
            As[cc][r] = feat[s_base[r] + (k0 + cc) * NN];
        }
        const float4* Wg = (const float4*)(Wn + k0 * DD);
        Bs[tid] = Wg[tid];
        Bs[tid + 256] = Wg[tid + 256];
        __syncthreads();
        #pragma unroll
        for (int cc = 0; cc < 16; cc++) {
            float4 bv = Bs[cc * 32 + tx];
            float4 a = *(float4*)&As[cc][ty * 4];
            float av[4] = {a.x, a.y, a.z, a.w};
            #pragma unroll
            for (int i = 0; i < 4; i++) {
                acc[i][0] += av[i] * bv.x; acc[i][1] += av[i] * bv.y;
                acc[i][2] += av[i] * bv.z; acc[i][3] += av[i] * bv.w;
            }
        }
        if (++cnt == 3) {
            cnt = 0;
            #pragma unroll
            for (int i = 0; i < 4; i++)
                #pragma unroll
                for (int q = 0; q < 4; q++) {
                    dacc[i][q] += (double)acc[i][q];
                    acc[i][q] = 0.f;
                }
        }
        __syncthreads();
    }
    float4 bb = ((const float4*)bnode)[tx];
    #pragma unroll
    for (int i = 0; i < 4; i++) {
        int r = ty * 4 + i;
        *(float4*)&Cs[r][tx * 4] = make_float4(
            (float)(dacc[i][0] + (double)bb.x), (float)(dacc[i][1] + (double)bb.y),
            (float)(dacc[i][2] + (double)bb.z), (float)(dacc[i][3] + (double)bb.w));
    }
    __syncthreads();
    // LayerNorm + GELU in double + fused L2-normalize, one warp per row
    int lane = tx, w = ty;
    for (int rr = 0; rr < 4; rr++) {
        int r = w + 8 * rr;
        double x[4];
        double s = 0.0;
        #pragma unroll
        for (int q = 0; q < 4; q++) { x[q] = (double)Cs[r][lane + 32 * q]; s += x[q]; }
        #pragma unroll
        for (int o = 16; o > 0; o >>= 1) s += __shfl_xor_sync(~0u, s, o);
        double mu = s * (1.0 / 128.0);
        double vs = 0.0;
        #pragma unroll
        for (int q = 0; q < 4; q++) { double d = x[q] - mu; vs += d * d; }
        #pragma unroll
        for (int o = 16; o > 0; o >>= 1) vs += __shfl_xor_sync(~0u, vs, o);
        double rs = 1.0 / sqrt(vs * (1.0 / 128.0) + 1e-5);
        int row = m0 + r;
        float yf[4];
        double ssd = 0.0;
        #pragma unroll
        for (int q = 0; q < 4; q++) {
            int d = lane + 32 * q;
            double y = (x[q] - mu) * rs * (double)ln_g[d] + (double)ln_b[d];
            yf[q] = (float)gelu_exact_d(y);
            nodes_out[(size_t)row * DD + d] = yf[q];
            ssd += (double)yf[q] * yf[q];
        }
        #pragma unroll
        for (int o = 16; o > 0; o >>= 1) ssd += __shfl_xor_sync(~0u, ssd, o);
        double dinv = 1.0 / fmax(sqrt(ssd), 1e-12);
        if (lane == 0) g_dinv[row] = dinv;
        float inv = (float)dinv;
        #pragma unroll
        for (int q = 0; q < 4; q++)
            g_nrm[(size_t)row * DD + lane + 32 * q] = yf[q] * inv;
    }
}

// ---------------------------------------------------------------------------
// Kernel 4: sim = nrm @ nrm^T per batch. 32x32 tile, 64 threads, 4x4 micro,
// f32x2 packed FMA (rowpairs free from the float4 A fragment).
// ---------------------------------------------------------------------------
__global__ void sim_kernel() {
    __shared__ float As[32][36];
    __shared__ float Bs[32][36];
    int tid = threadIdx.x;
    const float* base = g_nrm + (size_t)blockIdx.z * (NN * DD);
    int by = blockIdx.y, bx = blockIdx.x;
    int tx = tid & 7, ty = tid >> 3;
    u64 acc2[2][4] = {};                       // rowpair p = rows (2p,2p+1), col j
    for (int k0 = 0; k0 < 128; k0 += 32) {
        #pragma unroll
        for (int it = 0; it < 4; it++) {
            int idx = tid + it * 64;                 // 0..255
            int r = idx >> 3, kg = (idx & 7) * 4;
            int na = by * 32 + r;
            float4 v = (na < NN) ? *(const float4*)(base + (size_t)na * DD + k0 + kg)
                                 : make_float4(0.f, 0.f, 0.f, 0.f);
            As[kg + 0][r] = v.x; As[kg + 1][r] = v.y; As[kg + 2][r] = v.z; As[kg + 3][r] = v.w;
            int ma = bx * 32 + r;
            float4 u = (ma < NN) ? *(const float4*)(base + (size_t)ma * DD + k0 + kg)
                                 : make_float4(0.f, 0.f, 0.f, 0.f);
            Bs[kg + 0][r] = u.x; Bs[kg + 1][r] = u.y; Bs[kg + 2][r] = u.z; Bs[kg + 3][r] = u.w;
        }
        __syncthreads();
        #pragma unroll
        for (int k = 0; k < 32; k++) {
            ulonglong2 av = *(const ulonglong2*)&As[k][ty * 4];
            u64 ap[2] = {av.x, av.y};
            float4 b = *(float4*)&Bs[k][tx * 4];
            u64 b2[4] = {pack2(b.x), pack2(b.y), pack2(b.z), pack2(b.w)};
            #pragma unroll
            for (int p = 0; p < 2; p++)
                #pragma unroll
                for (int j = 0; j < 4; j++) fma2(acc2[p][j], ap[p], b2[j]);
        }
        __syncthreads();
    }
    float accf[4][4];
    #pragma unroll
    for (int p = 0; p < 2; p++)
        #pragma unroll
        for (int j = 0; j < 4; j++) {
            float2 v = unpack2(acc2[p][j]);
            accf[2 * p][j] = v.x;
            accf[2 * p + 1][j] = v.y;
        }
    float* simb = g_sim + (size_t)blockIdx.z * (NN * NN);
    #pragma unroll
    for (int i = 0; i < 4; i++) {
        int n0 = by * 32 + ty * 4 + i;
        if (n0 >= NN) break;
        int mcol = bx * 32 + tx * 4;
        if (mcol + 3 < NN) {
            *(float4*)(simb + n0 * NN + mcol) =
                make_float4(accf[i][0], accf[i][1], accf[i][2], accf[i][3]);
        } else {
            #pragma unroll
            for (int j = 0; j < 4; j++)
                if (mcol + j < NN) simb[n0 * NN + mcol + j] = accf[i][j];
        }
    }
}

// ---------------------------------------------------------------------------
// Kernel 5a: fp32 top-16 candidates per row, 4 threads per row.
// Each thread scans a 4-aligned range {52,48,48,48} with stable strict->
// insertion; thread 0 of each row does a stable 4-way merge
// (value desc, index asc) -- identical semantics to a single full scan.
// ---------------------------------------------------------------------------
__global__ void cand_kernel() {
    __shared__ float sval[64][4][NC];
    __shared__ int   sidx[64][4][NC];
    int tid = threadIdx.x;
    int rl = tid >> 2, q = tid & 3;
    int t = blockIdx.x * 64 + rl;
    int b = t / NN, n = t % NN;
    const float* row = g_sim + (size_t)b * (NN * NN) + n * NN;
    const int starts[5] = {0, 52, 100, 148, 196};
    int st = starts[q], en = starts[q + 1];
    float val[NC]; int idx[NC];
    #pragma unroll
    for (int i = 0; i < NC; i++) { val[i] = -1e30f; idx[i] = 0; }
    for (int m4 = st; m4 < en; m4 += 4) {
        float4 vv = *(const float4*)(row + m4);
        float vs[4] = {vv.x, vv.y, vv.z, vv.w};
        #pragma unroll
        for (int qq = 0; qq < 4; qq++) {
            int m = m4 + qq;
            if (m == n) continue;
            float v = vs[qq];
            if (v > val[NC - 1]) {
                int i = NC - 1;
                while (i > 0 && v > val[i - 1]) {
                    val[i] = val[i - 1]; idx[i] = idx[i - 1]; i--;
                }
                val[i] = v; idx[i] = m;
            }
        }
    }
    #pragma unroll
    for (int i = 0; i < NC; i++) { sval[rl][q][i] = val[i]; sidx[rl][q][i] = idx[i]; }
    __syncthreads();
    if (q == 0) {
        int p[4] = {0, 0, 0, 0};
        #pragma unroll
        for (int k = 0; k < NC; k++) {
            float bv = -1e38f; int bi = 0x7fffffff, bj = 0;
            #pragma unroll
            for (int j = 0; j < 4; j++) {
                if (p[j] < NC) {
                    float v = sval[rl][j][p[j]];
                    int id = sidx[rl][j][p[j]];
                    if (v > bv || (v == bv && id < bi)) { bv = v; bi = id; bj = j; }
                }
            }
            g_cand[t * NC + k] = bi;
            p[bj]++;
        }
    }
}

// ---------------------------------------------------------------------------
// Kernel 5b: exact re-rank in double; fp32 round; stable sort; emit top-8.
// ---------------------------------------------------------------------------
__global__ void refine_kernel(const float* __restrict__ nodes, float* __restrict__ adj_out) {
    __shared__ float skey[8][NC];
    __shared__ int   sidx[8][NC];
    int wip = threadIdx.x >> 5;
    int lane = threadIdx.x & 31;
    int t = blockIdx.x * 8 + wip;
    if (t >= M_NODES) return;
    int b = t / NN;
    int rowbase = b * NN;
    double dinv_n = g_dinv[t];
    float4 av = ((const float4*)(nodes + (size_t)t * DD))[lane];
    int myc = (lane < NC) ? g_cand[t * NC + lane] : 0;
    #pragma unroll
    for (int c = 0; c < NC; c++) {
        int j = __shfl_sync(~0u, myc, c);
        float4 bv = ((const float4*)(nodes + (size_t)(rowbase + j) * DD))[lane];
        double p = (double)av.x * bv.x + (double)av.y * bv.y
                 + (double)av.z * bv.z + (double)av.w * bv.w;
        #pragma unroll
        for (int o = 16; o > 0; o >>= 1) p += __shfl_xor_sync(~0u, p, o);
        if (lane == c) {
            double sim = p * dinv_n * g_dinv[rowbase + j];
            skey[wip][c] = (float)sim;
            sidx[wip][c] = j;
        }
    }
    __syncwarp();
    if (lane == 0) {
        float kv[NC]; int ki[NC];
        #pragma unroll
        for (int i = 0; i < NC; i++) { kv[i] = skey[wip][i]; ki[i] = sidx[wip][i]; }
        #pragma unroll
        for (int i = 1; i < NC; i++) {
            float v = kv[i]; int id = ki[i];
            int p = i - 1;
            while (p >= 0 && (kv[p] < v || (kv[p] == v && ki[p] > id))) {
                kv[p + 1] = kv[p]; ki[p + 1] = ki[p]; p--;
            }
            kv[p + 1] = v; ki[p + 1] = id;
        }
        #pragma unroll
        for (int k = 0; k < TK; k++) {
            g_adj[t * TK + k] = ki[k];
            adj_out[t * TK + k] = (float)ki[k];
        }
    }
}

// ---------------------------------------------------------------------------
// Kernel 6: C{1,2} = nodes @ We1[seg*128 : seg*128+128].
// 64x128 tile, 256 threads, 8x4 micro, scalar FFMA (r8 skeleton).
// ---------------------------------------------------------------------------
__global__ void cgemm64_kernel(const float* __restrict__ nodes, const float* __restrict__ We1) {
    __shared__ float As[32][68];
    __shared__ float4 Bs[1024];
    int tid = threadIdx.x;
    int m0 = blockIdx.x * 64;
    int seg = blockIdx.y;
    float* C = seg ? g_c2 : g_c1;
    const float* W = We1 + (size_t)seg * 128 * DD;
    int tx = tid & 31, ty = tid >> 5;
    float acc[8][4] = {};
    for (int k0 = 0; k0 < 128; k0 += 32) {
        {
            int r = tid >> 2, cb = (tid & 3) * 8;
            const float4* p = (const float4*)(nodes + (size_t)(m0 + r) * DD + k0 + cb);
            float4 v0 = p[0], v1 = p[1];
            As[cb + 0][r] = v0.x; As[cb + 1][r] = v0.y; As[cb + 2][r] = v0.z; As[cb + 3][r] = v0.w;
            As[cb + 4][r] = v1.x; As[cb + 5][r] = v1.y; As[cb + 6][r] = v1.z; As[cb + 7][r] = v1.w;
        }
        {
            const float4* Wg = (const float4*)(W + k0 * DD);
            #pragma unroll
            for (int i = 0; i < 4; i++) Bs[tid + i * 256] = Wg[tid + i * 256];
        }
        __syncthreads();
        #pragma unroll
        for (int cc = 0; cc < 32; cc++) {
            float4 bv = Bs[cc * 32 + tx];
            float4 a0 = *(float4*)&As[cc][ty * 8];
            float4 a1 = *(float4*)&As[cc][ty * 8 + 4];
            float ar[8] = {a0.x, a0.y, a0.z, a0.w, a1.x, a1.y, a1.z, a1.w};
            #pragma unroll
            for (int i = 0; i < 8; i++) {
                acc[i][0] += ar[i] * bv.x; acc[i][1] += ar[i] * bv.y;
                acc[i][2] += ar[i] * bv.z; acc[i][3] += ar[i] * bv.w;
            }
        }
        __syncthreads();
    }
    #pragma unroll
    for (int i = 0; i < 8; i++) {
        int row = m0 + ty * 8 + i;
        ((float4*)(C + (size_t)row * DD))[tx] =
            make_float4(acc[i][0], acc[i][1], acc[i][2], acc[i][3]);
    }
}

// ---------------------------------------------------------------------------
// Kernel 7: C3 = table @ We1[256:384] + be1 (729 rows, tiny).
// ---------------------------------------------------------------------------
__global__ void c3_kernel(const float* __restrict__ We1, const float* __restrict__ be1) {
    __shared__ float ts[128];
    int row = blockIdx.x, t = threadIdx.x;
    ts[t] = g_table[row * DD + t];
    __syncthreads();
    float acc = be1[t];
    const float* W = We1 + (size_t)256 * DD;
    #pragma unroll 8
    for (int k = 0; k < 128; k++) acc += ts[k] * W[k * DD + t];
    g_c3[row * DD + t] = acc;
}

// ---------------------------------------------------------------------------
// Kernel 8: edges = GELU(C1[n] + C2[adj] + C3[disp]) @ We2 + be2.
// Double-buffered 64x128 tile, 8x4 micro. Gather LDGs for chunk c+1 are
// issued BEFORE the FMA block of chunk c (latency hidden under compute);
// GELU + STS happen after. Same k-order => bit-identical results.
// ---------------------------------------------------------------------------
__global__ void edge_fused64_kernel(const float* __restrict__ We2, const float* __restrict__ be2,
                                    float* __restrict__ edges_out) {
    __shared__ float As[2][32][68];
    __shared__ float4 Bs[2][1024];
    __shared__ int s1[64], s2[64], s3[64];
    int tid = threadIdx.x;
    int m0 = blockIdx.x * 64;
    if (tid < 64) {
        int e = m0 + tid;
        int bn = e >> 3;
        int b = bn / NN, n = bn - b * NN;
        int j = g_adj[e];
        s1[tid] = bn * DD;
        s2[tid] = (b * NN + j) * DD;
        int rn = n / 14, cn = n % 14, rj = j / 14, cj = j % 14;
        s3[tid] = ((rj - rn + 13) * 27 + (cj - cn + 13)) * DD;
    }
    __syncthreads();
    int tx = tid & 31, ty = tid >> 5;
    int gr = tid >> 2, gc = (tid & 3) * 8;     // gather: 4 threads per row, 8 floats each
    float acc[8][4] = {};

    // fill chunk 0 into buffer 0
    {
        const float* p1 = g_c1 + s1[gr] + gc;
        const float* p2 = g_c2 + s2[gr] + gc;
        const float* p3 = g_c3 + s3[gr] + gc;
        #pragma unroll
        for (int q = 0; q < 2; q++) {
            float4 v1 = *(const float4*)(p1 + q * 4);
            float4 v2 = *(const float4*)(p2 + q * 4);
            float4 v3 = *(const float4*)(p3 + q * 4);
            As[0][gc + q * 4 + 0][gr] = gelu_exact(v1.x + v2.x + v3.x);
            As[0][gc + q * 4 + 1][gr] = gelu_exact(v1.y + v2.y + v3.y);
            As[0][gc + q * 4 + 2][gr] = gelu_exact(v1.z + v2.z + v3.z);
            As[0][gc + q * 4 + 3][gr] = gelu_exact(v1.w + v2.w + v3.w);
        }
        const float4* Wg = (const float4*)We2;
        #pragma unroll
        for (int i = 0; i < 4; i++) Bs[0][tid + i * 256] = Wg[tid + i * 256];
    }
    __syncthreads();

    #pragma unroll
    for (int c = 0; c < 4; c++) {
        int buf = c & 1;
        float4 pre[6], bpre[4];
        if (c < 3) {
            int kn = (c + 1) * 32;
            const float* p1 = g_c1 + s1[gr] + kn + gc;
            const float* p2 = g_c2 + s2[gr] + kn + gc;
            const float* p3 = g_c3 + s3[gr] + kn + gc;
            pre[0] = *(const float4*)(p1);     pre[1] = *(const float4*)(p1 + 4);
            pre[2] = *(const float4*)(p2);     pre[3] = *(const float4*)(p2 + 4);
            pre[4] = *(const float4*)(p3);     pre[5] = *(const float4*)(p3 + 4);
            const float4* Wg = (const float4*)(We2 + kn * DD);
            #pragma unroll
            for (int i = 0; i < 4; i++) bpre[i] = Wg[tid + i * 256];
        }
        // compute on current buffer
        #pragma unroll
        for (int cc = 0; cc < 32; cc++) {
            float4 bv = Bs[buf][cc * 32 + tx];
            float4 a0 = *(float4*)&As[buf][cc][ty * 8];
            float4 a1 = *(float4*)&As[buf][cc][ty * 8 + 4];
            float ar[8] = {a0.x, a0.y, a0.z, a0.w, a1.x, a1.y, a1.z, a1.w};
            #pragma unroll
            for (int i = 0; i < 8; i++) {
                acc[i][0] += ar[i] * bv.x; acc[i][1] += ar[i] * bv.y;
                acc[i][2] += ar[i] * bv.z; acc[i][3] += ar[i] * bv.w;
            }
        }
        if (c < 3) {
            int nb = buf ^ 1;
            #pragma unroll
            for (int q = 0; q < 2; q++) {
                float4 v1 = pre[q], v2 = pre[2 + q], v3 = pre[4 + q];
                As[nb][gc + q * 4 + 0][gr] = gelu_exact(v1.x + v2.x + v3.x);
                As[nb][gc + q * 4 + 1][gr] = gelu_exact(v1.y + v2.y + v3.y);
                As[nb][gc + q * 4 + 2][gr] = gelu_exact(v1.z + v2.z + v3.z);
                As[nb][gc + q * 4 + 3][gr] = gelu_exact(v1.w + v2.w + v3.w);
            }
            #pragma unroll
            for (int i = 0; i < 4; i++) Bs[nb][tid + i * 256] = bpre[i];
        }
        __syncthreads();
    }

    float4 bb = ((const float4*)be2)[tx];
    #pragma unroll
    for (int i = 0; i < 8; i++) {
        int row = m0 + ty * 8 + i;
        ((float4*)(edges_out + (size_t)row * DD))[tx] =
            make_float4(acc[i][0] + bb.x, acc[i][1] + bb.y,
                        acc[i][2] + bb.z, acc[i][3] + bb.w);
    }
}

// ---------------------------------------------------------------------------
extern "C" void kernel_launch(void* const* d_in, const int* in_sizes, int n_in,
                              void* d_out, int out_size) {
    const float* feat = (const float*)d_in[0];
    const float* Wn   = (const float*)d_in[1];
    const float* bn   = (const float*)d_in[2];
    const float* lng  = (const float*)d_in[3];
    const float* lnb  = (const float*)d_in[4];
    const float* Wp1  = (const float*)d_in[5];
    const float* bp1  = (const float*)d_in[6];
    const float* Wp2  = (const float*)d_in[7];
    const float* bp2  = (const float*)d_in[8];
    const float* We1  = (const float*)d_in[9];
    const float* be1  = (const float*)d_in[10];
    const float* We2  = (const float*)d_in[11];
    const float* be2  = (const float*)d_in[12];

    float* out = (float*)d_out;
    float* nodes_out = out;                                   // B*N*D
    float* edges_out = out + (size_t)M_NODES * DD;            // B*N*K*D
    float* adj_out   = edges_out + (size_t)NE * DD;           // B*N*K

    pos_table_kernel<<<729, 128>>>(Wp1, bp1, Wp2, bp2);
    node_kernel<<<M_NODES / 32, 256>>>(feat, Wn, bn, lng, lnb, nodes_out);
    sim_kernel<<<dim3(7, 7, BB), 64>>>();
    cand_kernel<<<M_NODES / 64, 256>>>();
    refine_kernel<<<(M_NODES + 7) / 8, 256>>>(nodes_out, adj_out);
    cgemm64_kernel<<<dim3(M_NODES / 64, 2), 256>>>(nodes_out, We1);
    c3_kernel<<<729, 128>>>(We1, be1);
    edge_fused64_kernel<<<NE / 64, 256>>>(We2, be2, edges_out);
}

// round 11
// speedup vs baseline: 2.2011x; 1.1812x over previous
#include <cuda_runtime.h>
#include <math.h>

// Problem constants
#define BB 128
#define CC 768
#define NN 196
#define DD 128
#define TK 8
#define NC 16                      // candidate count for exact re-rank
#define M_NODES (BB * NN)          // 25088
#define NE      (M_NODES * TK)     // 200704

typedef unsigned long long u64;

// Scratch (device globals; no allocations allowed)
__device__ float  g_nrm[M_NODES * DD];          // normalized nodes (fp32, candidate stage)
__device__ float  g_sim[BB * NN * NN];          // similarity (fp32, candidate stage)
__device__ double g_dinv[M_NODES];              // double 1/||node||
__device__ int    g_cand[M_NODES * NC];         // top-16 fp32 candidates
__device__ int    g_adj[NE];                    // final top-8 indices
__device__ float  g_table[27 * 27 * DD];        // pos-MLP table
__device__ float  g_c1[M_NODES * DD];           // nodes @ We1[0:128]
__device__ float  g_c2[M_NODES * DD];           // nodes @ We1[128:256]
__device__ float  g_c3[27 * 27 * DD];           // table @ We1[256:384] + be1

__device__ __forceinline__ float gelu_exact(float x) {
    return 0.5f * x * (1.0f + erff(x * 0.70710678118654752440f));
}
__device__ __forceinline__ double gelu_exact_d(double x) {
    return 0.5 * x * (1.0 + erf(x * 0.7071067811865475244));
}

// ---- packed f32x2 helpers (used by sim kernel; IEEE per-lane) ----
__device__ __forceinline__ u64 pack2(float x) {
    unsigned int u = __float_as_uint(x);
    u64 r;
    asm("mov.b64 %0, {%1, %1};" : "=l"(r) : "r"(u));
    return r;
}
__device__ __forceinline__ void fma2(u64& d, u64 a, u64 b) {
    asm("fma.rn.f32x2 %0, %1, %2, %0;" : "+l"(d) : "l"(a), "l"(b));
}
__device__ __forceinline__ float2 unpack2(u64 v) {
    unsigned int lo, hi;
    asm("mov.b64 {%0, %1}, %2;" : "=r"(lo), "=r"(hi) : "l"(v));
    return make_float2(__uint_as_float(lo), __uint_as_float(hi));
}

// ---------------------------------------------------------------------------
// Kernel 1: pos-MLP table. disp has only 27x27 distinct values (i/13 grid).
// ---------------------------------------------------------------------------
__global__ void pos_table_kernel(const float* __restrict__ Wp1, const float* __restrict__ bp1,
                                 const float* __restrict__ Wp2, const float* __restrict__ bp2) {
    __shared__ float h[64];
    int idx = blockIdx.x;
    float dy = (float)(idx / 27 - 13) * (1.0f / 13.0f);
    float dx = (float)(idx % 27 - 13) * (1.0f / 13.0f);
    int t = threadIdx.x;
    if (t < 64) {
        float v = dy * Wp1[t] + dx * Wp1[64 + t] + bp1[t];
        h[t] = gelu_exact(v);
    }
    __syncthreads();
    float acc = bp2[t];
    #pragma unroll 8
    for (int i = 0; i < 64; i++) acc += h[i] * Wp2[i * DD + t];
    g_table[idx * DD + t] = acc;
}

// ---------------------------------------------------------------------------
// Kernel 2: nodes = GELU(LN(tokens @ W_node + b_node)), fused L2-normalize.
// 32-row tile, 256 threads, 4x4 micro (low regs -> 3 blocks/SM).
// Chunked-double accumulation (48 k per DADD); LN+GELU in double.
// Writes nodes_out, g_nrm, g_dinv.
// ---------------------------------------------------------------------------
__global__ void node_kernel(const float* __restrict__ feat, const float* __restrict__ Wn,
                            const float* __restrict__ bnode, const float* __restrict__ ln_g,
                            const float* __restrict__ ln_b, float* __restrict__ nodes_out) {
    __shared__ float As[16][36];
    __shared__ float4 Bs[16 * 32];
    __shared__ float Cs[32][132];
    __shared__ int s_base[32];
    int tid = threadIdx.x;
    int m0 = blockIdx.x * 32;
    if (tid < 32) {
        int m = m0 + tid;
        int b = m / NN, n = m % NN;
        s_base[tid] = b * (CC * NN) + n;
    }
    int tx = tid & 31, ty = tid >> 5;
    double dacc[4][4];
    #pragma unroll
    for (int i = 0; i < 4; i++)
        #pragma unroll
        for (int q = 0; q < 4; q++) dacc[i][q] = 0.0;
    float acc[4][4] = {};
    int cnt = 0;
    __syncthreads();
    for (int k0 = 0; k0 < CC; k0 += 16) {
        #pragma unroll
        for (int i = 0; i < 2; i++) {
            int e = tid + i * 256;
            int r = e & 31, cc = e >> 5;
            As[cc][r] = feat[s_base[r] + (k0 + cc) * NN];
        }
        const float4* Wg = (const float4*)(Wn + k0 * DD);
        Bs[tid] = Wg[tid];
        Bs[tid + 256] = Wg[tid + 256];
        __syncthreads();
        #pragma unroll
        for (int cc = 0; cc < 16; cc++) {
            float4 bv = Bs[cc * 32 + tx];
            float4 a = *(float4*)&As[cc][ty * 4];
            float av[4] = {a.x, a.y, a.z, a.w};
            #pragma unroll
            for (int i = 0; i < 4; i++) {
                acc[i][0] += av[i] * bv.x; acc[i][1] += av[i] * bv.y;
                acc[i][2] += av[i] * bv.z; acc[i][3] += av[i] * bv.w;
            }
        }
        if (++cnt == 3) {
            cnt = 0;
            #pragma unroll
            for (int i = 0; i < 4; i++)
                #pragma unroll
                for (int q = 0; q < 4; q++) {
                    dacc[i][q] += (double)acc[i][q];
                    acc[i][q] = 0.f;
                }
        }
        __syncthreads();
    }
    float4 bb = ((const float4*)bnode)[tx];
    #pragma unroll
    for (int i = 0; i < 4; i++) {
        int r = ty * 4 + i;
        *(float4*)&Cs[r][tx * 4] = make_float4(
            (float)(dacc[i][0] + (double)bb.x), (float)(dacc[i][1] + (double)bb.y),
            (float)(dacc[i][2] + (double)bb.z), (float)(dacc[i][3] + (double)bb.w));
    }
    __syncthreads();
    // LayerNorm + GELU in double + fused L2-normalize, one warp per row
    int lane = tx, w = ty;
    for (int rr = 0; rr < 4; rr++) {
        int r = w + 8 * rr;
        double x[4];
        double s = 0.0;
        #pragma unroll
        for (int q = 0; q < 4; q++) { x[q] = (double)Cs[r][lane + 32 * q]; s += x[q]; }
        #pragma unroll
        for (int o = 16; o > 0; o >>= 1) s += __shfl_xor_sync(~0u, s, o);
        double mu = s * (1.0 / 128.0);
        double vs = 0.0;
        #pragma unroll
        for (int q = 0; q < 4; q++) { double d = x[q] - mu; vs += d * d; }
        #pragma unroll
        for (int o = 16; o > 0; o >>= 1) vs += __shfl_xor_sync(~0u, vs, o);
        double rs = 1.0 / sqrt(vs * (1.0 / 128.0) + 1e-5);
        int row = m0 + r;
        float yf[4];
        double ssd = 0.0;
        #pragma unroll
        for (int q = 0; q < 4; q++) {
            int d = lane + 32 * q;
            double y = (x[q] - mu) * rs * (double)ln_g[d] + (double)ln_b[d];
            yf[q] = (float)gelu_exact_d(y);
            nodes_out[(size_t)row * DD + d] = yf[q];
            ssd += (double)yf[q] * yf[q];
        }
        #pragma unroll
        for (int o = 16; o > 0; o >>= 1) ssd += __shfl_xor_sync(~0u, ssd, o);
        double dinv = 1.0 / fmax(sqrt(ssd), 1e-12);
        if (lane == 0) g_dinv[row] = dinv;
        float inv = (float)dinv;
        #pragma unroll
        for (int q = 0; q < 4; q++)
            g_nrm[(size_t)row * DD + lane + 32 * q] = yf[q] * inv;
    }
}

// ---------------------------------------------------------------------------
// Kernel 4: sim = nrm @ nrm^T per batch. 32x32 tile, 64 threads, 4x4 micro,
// f32x2 packed FMA (rowpairs free from the float4 A fragment).
// ---------------------------------------------------------------------------
__global__ void sim_kernel() {
    __shared__ float As[32][36];
    __shared__ float Bs[32][36];
    int tid = threadIdx.x;
    const float* base = g_nrm + (size_t)blockIdx.z * (NN * DD);
    int by = blockIdx.y, bx = blockIdx.x;
    int tx = tid & 7, ty = tid >> 3;
    u64 acc2[2][4] = {};                       // rowpair p = rows (2p,2p+1), col j
    for (int k0 = 0; k0 < 128; k0 += 32) {
        #pragma unroll
        for (int it = 0; it < 4; it++) {
            int idx = tid + it * 64;                 // 0..255
            int r = idx >> 3, kg = (idx & 7) * 4;
            int na = by * 32 + r;
            float4 v = (na < NN) ? *(const float4*)(base + (size_t)na * DD + k0 + kg)
                                 : make_float4(0.f, 0.f, 0.f, 0.f);
            As[kg + 0][r] = v.x; As[kg + 1][r] = v.y; As[kg + 2][r] = v.z; As[kg + 3][r] = v.w;
            int ma = bx * 32 + r;
            float4 u = (ma < NN) ? *(const float4*)(base + (size_t)ma * DD + k0 + kg)
                                 : make_float4(0.f, 0.f, 0.f, 0.f);
            Bs[kg + 0][r] = u.x; Bs[kg + 1][r] = u.y; Bs[kg + 2][r] = u.z; Bs[kg + 3][r] = u.w;
        }
        __syncthreads();
        #pragma unroll
        for (int k = 0; k < 32; k++) {
            ulonglong2 av = *(const ulonglong2*)&As[k][ty * 4];
            u64 ap[2] = {av.x, av.y};
            float4 b = *(float4*)&Bs[k][tx * 4];
            u64 b2[4] = {pack2(b.x), pack2(b.y), pack2(b.z), pack2(b.w)};
            #pragma unroll
            for (int p = 0; p < 2; p++)
                #pragma unroll
                for (int j = 0; j < 4; j++) fma2(acc2[p][j], ap[p], b2[j]);
        }
        __syncthreads();
    }
    float accf[4][4];
    #pragma unroll
    for (int p = 0; p < 2; p++)
        #pragma unroll
        for (int j = 0; j < 4; j++) {
            float2 v = unpack2(acc2[p][j]);
            accf[2 * p][j] = v.x;
            accf[2 * p + 1][j] = v.y;
        }
    float* simb = g_sim + (size_t)blockIdx.z * (NN * NN);
    #pragma unroll
    for (int i = 0; i < 4; i++) {
        int n0 = by * 32 + ty * 4 + i;
        if (n0 >= NN) break;
        int mcol = bx * 32 + tx * 4;
        if (mcol + 3 < NN) {
            *(float4*)(simb + n0 * NN + mcol) =
                make_float4(accf[i][0], accf[i][1], accf[i][2], accf[i][3]);
        } else {
            #pragma unroll
            for (int j = 0; j < 4; j++)
                if (mcol + j < NN) simb[n0 * NN + mcol + j] = accf[i][j];
        }
    }
}

// ---------------------------------------------------------------------------
// Kernel 5a: top-16 candidates, one WARP per row.
// Lane l loads elements l+32j (coalesced, 7 upfront LDGs -> MLP=7), sorts its
// 7 locally via odd-even transposition network (static indices, no spills),
// then 16 rounds of warp argmax extraction (value desc, index asc tiebreak).
// Produces the exact same stable top-16 as a full sequential scan.
// ---------------------------------------------------------------------------
__global__ void cand_kernel() {
    int w = (blockIdx.x * blockDim.x + threadIdx.x) >> 5;   // row id
    int lane = threadIdx.x & 31;
    if (w >= M_NODES) return;
    int b = w / NN, n = w % NN;
    const float* row = g_sim + (size_t)b * (NN * NN) + n * NN;

    float v0, v1, v2, v3, v4, v5, v6;
    int   i0, i1, i2, i3, i4, i5, i6;
    {
        int m;
        m = lane;        i0 = m; v0 = (m != n) ? row[m] : -1e38f;
        m = lane + 32;   i1 = m; v1 = (m != n) ? row[m] : -1e38f;
        m = lane + 64;   i2 = m; v2 = (m != n) ? row[m] : -1e38f;
        m = lane + 96;   i3 = m; v3 = (m != n) ? row[m] : -1e38f;
        m = lane + 128;  i4 = m; v4 = (m != n) ? row[m] : -1e38f;
        m = lane + 160;  i5 = m; v5 = (m != n) ? row[m] : -1e38f;
        m = lane + 192;  i6 = m; v6 = (m < NN && m != n) ? row[m] : -1e38f;
    }
    // descending sort (value desc, index asc): odd-even transposition, 7 rounds
    #define CSWP(va, ia, vb, ib)                                             \
        { bool sw = (va < vb) || (va == vb && ia > ib);                      \
          float tv = sw ? vb : va; vb = sw ? va : vb; va = tv;               \
          int ti = sw ? ib : ia;   ib = sw ? ia : ib; ia = ti; }
    #pragma unroll
    for (int rnd = 0; rnd < 4; rnd++) {
        CSWP(v0, i0, v1, i1); CSWP(v2, i2, v3, i3); CSWP(v4, i4, v5, i5);
        if (rnd < 3) { CSWP(v1, i1, v2, i2); CSWP(v3, i3, v4, i4); CSWP(v5, i5, v6, i6); }
    }
    #undef CSWP

    int res = 0;
    #pragma unroll
    for (int k = 0; k < NC; k++) {
        float bv = v0; int bi = i0, bl = lane;
        #pragma unroll
        for (int o = 16; o > 0; o >>= 1) {
            float ov = __shfl_xor_sync(~0u, bv, o);
            int   oi = __shfl_xor_sync(~0u, bi, o);
            int   ol = __shfl_xor_sync(~0u, bl, o);
            bool take = (ov > bv) || (ov == bv && oi < bi);
            bv = take ? ov : bv; bi = take ? oi : bi; bl = take ? ol : bl;
        }
        if (lane == bl) {   // winner pops its head (static shifts)
            v0 = v1; i0 = i1; v1 = v2; i1 = i2; v2 = v3; i2 = i3;
            v3 = v4; i3 = i4; v4 = v5; i4 = i5; v5 = v6; i5 = i6;
            v6 = -1e38f;
        }
        if (lane == k) res = bi;
    }
    if (lane < NC) g_cand[w * NC + lane] = res;
}

// ---------------------------------------------------------------------------
// Kernel 5b: exact re-rank in double; fp32 round; stable sort; emit top-8.
// ---------------------------------------------------------------------------
__global__ void refine_kernel(const float* __restrict__ nodes, float* __restrict__ adj_out) {
    __shared__ float skey[8][NC];
    __shared__ int   sidx[8][NC];
    int wip = threadIdx.x >> 5;
    int lane = threadIdx.x & 31;
    int t = blockIdx.x * 8 + wip;
    if (t >= M_NODES) return;
    int b = t / NN;
    int rowbase = b * NN;
    double dinv_n = g_dinv[t];
    float4 av = ((const float4*)(nodes + (size_t)t * DD))[lane];
    int myc = (lane < NC) ? g_cand[t * NC + lane] : 0;
    #pragma unroll
    for (int c = 0; c < NC; c++) {
        int j = __shfl_sync(~0u, myc, c);
        float4 bv = ((const float4*)(nodes + (size_t)(rowbase + j) * DD))[lane];
        double p = (double)av.x * bv.x + (double)av.y * bv.y
                 + (double)av.z * bv.z + (double)av.w * bv.w;
        #pragma unroll
        for (int o = 16; o > 0; o >>= 1) p += __shfl_xor_sync(~0u, p, o);
        if (lane == c) {
            double sim = p * dinv_n * g_dinv[rowbase + j];
            skey[wip][c] = (float)sim;
            sidx[wip][c] = j;
        }
    }
    __syncwarp();
    if (lane == 0) {
        float kv[NC]; int ki[NC];
        #pragma unroll
        for (int i = 0; i < NC; i++) { kv[i] = skey[wip][i]; ki[i] = sidx[wip][i]; }
        #pragma unroll
        for (int i = 1; i < NC; i++) {
            float v = kv[i]; int id = ki[i];
            int p = i - 1;
            while (p >= 0 && (kv[p] < v || (kv[p] == v && ki[p] > id))) {
                kv[p + 1] = kv[p]; ki[p + 1] = ki[p]; p--;
            }
            kv[p + 1] = v; ki[p + 1] = id;
        }
        #pragma unroll
        for (int k = 0; k < TK; k++) {
            g_adj[t * TK + k] = ki[k];
            adj_out[t * TK + k] = (float)ki[k];
        }
    }
}

// ---------------------------------------------------------------------------
// Kernel 6: C{1,2} = nodes @ We1[seg*128 : seg*128+128].
// 64x128 tile, 256 threads, 8x4 micro, scalar FFMA (r8 skeleton).
// ---------------------------------------------------------------------------
__global__ void cgemm64_kernel(const float* __restrict__ nodes, const float* __restrict__ We1) {
    __shared__ float As[32][68];
    __shared__ float4 Bs[1024];
    int tid = threadIdx.x;
    int m0 = blockIdx.x * 64;
    int seg = blockIdx.y;
    float* C = seg ? g_c2 : g_c1;
    const float* W = We1 + (size_t)seg * 128 * DD;
    int tx = tid & 31, ty = tid >> 5;
    float acc[8][4] = {};
    for (int k0 = 0; k0 < 128; k0 += 32) {
        {
            int r = tid >> 2, cb = (tid & 3) * 8;
            const float4* p = (const float4*)(nodes + (size_t)(m0 + r) * DD + k0 + cb);
            float4 v0 = p[0], v1 = p[1];
            As[cb + 0][r] = v0.x; As[cb + 1][r] = v0.y; As[cb + 2][r] = v0.z; As[cb + 3][r] = v0.w;
            As[cb + 4][r] = v1.x; As[cb + 5][r] = v1.y; As[cb + 6][r] = v1.z; As[cb + 7][r] = v1.w;
        }
        {
            const float4* Wg = (const float4*)(W + k0 * DD);
            #pragma unroll
            for (int i = 0; i < 4; i++) Bs[tid + i * 256] = Wg[tid + i * 256];
        }
        __syncthreads();
        #pragma unroll
        for (int cc = 0; cc < 32; cc++) {
            float4 bv = Bs[cc * 32 + tx];
            float4 a0 = *(float4*)&As[cc][ty * 8];
            float4 a1 = *(float4*)&As[cc][ty * 8 + 4];
            float ar[8] = {a0.x, a0.y, a0.z, a0.w, a1.x, a1.y, a1.z, a1.w};
            #pragma unroll
            for (int i = 0; i < 8; i++) {
                acc[i][0] += ar[i] * bv.x; acc[i][1] += ar[i] * bv.y;
                acc[i][2] += ar[i] * bv.z; acc[i][3] += ar[i] * bv.w;
            }
        }
        __syncthreads();
    }
    #pragma unroll
    for (int i = 0; i < 8; i++) {
        int row = m0 + ty * 8 + i;
        ((float4*)(C + (size_t)row * DD))[tx] =
            make_float4(acc[i][0], acc[i][1], acc[i][2], acc[i][3]);
    }
}

// ---------------------------------------------------------------------------
// Kernel 7: C3 = table @ We1[256:384] + be1 (729 rows, tiny).
// ---------------------------------------------------------------------------
__global__ void c3_kernel(const float* __restrict__ We1, const float* __restrict__ be1) {
    __shared__ float ts[128];
    int row = blockIdx.x, t = threadIdx.x;
    ts[t] = g_table[row * DD + t];
    __syncthreads();
    float acc = be1[t];
    const float* W = We1 + (size_t)256 * DD;
    #pragma unroll 8
    for (int k = 0; k < 128; k++) acc += ts[k] * W[k * DD + t];
    g_c3[row * DD + t] = acc;
}

// ---------------------------------------------------------------------------
// Kernel 8: edges = GELU(C1[n] + C2[adj] + C3[disp]) @ We2 + be2.
// Double-buffered 64x128 tile, 8x4 micro. Gather LDGs for chunk c+1 are
// issued BEFORE the FMA block of chunk c (latency hidden under compute);
// GELU + STS happen after. Same k-order => bit-identical results.
// ---------------------------------------------------------------------------
__global__ void edge_fused64_kernel(const float* __restrict__ We2, const float* __restrict__ be2,
                                    float* __restrict__ edges_out) {
    __shared__ float As[2][32][68];
    __shared__ float4 Bs[2][1024];
    __shared__ int s1[64], s2[64], s3[64];
    int tid = threadIdx.x;
    int m0 = blockIdx.x * 64;
    if (tid < 64) {
        int e = m0 + tid;
        int bn = e >> 3;
        int b = bn / NN, n = bn - b * NN;
        int j = g_adj[e];
        s1[tid] = bn * DD;
        s2[tid] = (b * NN + j) * DD;
        int rn = n / 14, cn = n % 14, rj = j / 14, cj = j % 14;
        s3[tid] = ((rj - rn + 13) * 27 + (cj - cn + 13)) * DD;
    }
    __syncthreads();
    int tx = tid & 31, ty = tid >> 5;
    int gr = tid >> 2, gc = (tid & 3) * 8;     // gather: 4 threads per row, 8 floats each
    float acc[8][4] = {};

    // fill chunk 0 into buffer 0
    {
        const float* p1 = g_c1 + s1[gr] + gc;
        const float* p2 = g_c2 + s2[gr] + gc;
        const float* p3 = g_c3 + s3[gr] + gc;
        #pragma unroll
        for (int q = 0; q < 2; q++) {
            float4 v1 = *(const float4*)(p1 + q * 4);
            float4 v2 = *(const float4*)(p2 + q * 4);
            float4 v3 = *(const float4*)(p3 + q * 4);
            As[0][gc + q * 4 + 0][gr] = gelu_exact(v1.x + v2.x + v3.x);
            As[0][gc + q * 4 + 1][gr] = gelu_exact(v1.y + v2.y + v3.y);
            As[0][gc + q * 4 + 2][gr] = gelu_exact(v1.z + v2.z + v3.z);
            As[0][gc + q * 4 + 3][gr] = gelu_exact(v1.w + v2.w + v3.w);
        }
        const float4* Wg = (const float4*)We2;
        #pragma unroll
        for (int i = 0; i < 4; i++) Bs[0][tid + i * 256] = Wg[tid + i * 256];
    }
    __syncthreads();

    #pragma unroll
    for (int c = 0; c < 4; c++) {
        int buf = c & 1;
        float4 pre[6], bpre[4];
        if (c < 3) {
            int kn = (c + 1) * 32;
            const float* p1 = g_c1 + s1[gr] + kn + gc;
            const float* p2 = g_c2 + s2[gr] + kn + gc;
            const float* p3 = g_c3 + s3[gr] + kn + gc;
            pre[0] = *(const float4*)(p1);     pre[1] = *(const float4*)(p1 + 4);
            pre[2] = *(const float4*)(p2);     pre[3] = *(const float4*)(p2 + 4);
            pre[4] = *(const float4*)(p3);     pre[5] = *(const float4*)(p3 + 4);
            const float4* Wg = (const float4*)(We2 + kn * DD);
            #pragma unroll
            for (int i = 0; i < 4; i++) bpre[i] = Wg[tid + i * 256];
        }
        // compute on current buffer
        #pragma unroll
        for (int cc = 0; cc < 32; cc++) {
            float4 bv = Bs[buf][cc * 32 + tx];
            float4 a0 = *(float4*)&As[buf][cc][ty * 8];
            float4 a1 = *(float4*)&As[buf][cc][ty * 8 + 4];
            float ar[8] = {a0.x, a0.y, a0.z, a0.w, a1.x, a1.y, a1.z, a1.w};
            #pragma unroll
            for (int i = 0; i < 8; i++) {
                acc[i][0] += ar[i] * bv.x; acc[i][1] += ar[i] * bv.y;
                acc[i][2] += ar[i] * bv.z; acc[i][3] += ar[i] * bv.w;
            }
        }
        if (c < 3) {
            int nb = buf ^ 1;
            #pragma unroll
            for (int q = 0; q < 2; q++) {
                float4 v1 = pre[q], v2 = pre[2 + q], v3 = pre[4 + q];
                As[nb][gc + q * 4 + 0][gr] = gelu_exact(v1.x + v2.x + v3.x);
                As[nb][gc + q * 4 + 1][gr] = gelu_exact(v1.y + v2.y + v3.y);
                As[nb][gc + q * 4 + 2][gr] = gelu_exact(v1.z + v2.z + v3.z);
                As[nb][gc + q * 4 + 3][gr] = gelu_exact(v1.w + v2.w + v3.w);
            }
            #pragma unroll
            for (int i = 0; i < 4; i++) Bs[nb][tid + i * 256] = bpre[i];
        }
        __syncthreads();
    }

    float4 bb = ((const float4*)be2)[tx];
    #pragma unroll
    for (int i = 0; i < 8; i++) {
        int row = m0 + ty * 8 + i;
        ((float4*)(edges_out + (size_t)row * DD))[tx] =
            make_float4(acc[i][0] + bb.x, acc[i][1] + bb.y,
                        acc[i][2] + bb.z, acc[i][3] + bb.w);
    }
}

// ---------------------------------------------------------------------------
extern "C" void kernel_launch(void* const* d_in, const int* in_sizes, int n_in,
                              void* d_out, int out_size) {
    const float* feat = (const float*)d_in[0];
    const float* Wn   = (const float*)d_in[1];
    const float* bn   = (const float*)d_in[2];
    const float* lng  = (const float*)d_in[3];
    const float* lnb  = (const float*)d_in[4];
    const float* Wp1  = (const float*)d_in[5];
    const float* bp1  = (const float*)d_in[6];
    const float* Wp2  = (const float*)d_in[7];
    const float* bp2  = (const float*)d_in[8];
    const float* We1  = (const float*)d_in[9];
    const float* be1  = (const float*)d_in[10];
    const float* We2  = (const float*)d_in[11];
    const float* be2  = (const float*)d_in[12];

    float* out = (float*)d_out;
    float* nodes_out = out;                                   // B*N*D
    float* edges_out = out + (size_t)M_NODES * DD;            // B*N*K*D
    float* adj_out   = edges_out + (size_t)NE * DD;           // B*N*K

    pos_table_kernel<<<729, 128>>>(Wp1, bp1, Wp2, bp2);
    node_kernel<<<M_NODES / 32, 256>>>(feat, Wn, bn, lng, lnb, nodes_out);
    sim_kernel<<<dim3(7, 7, BB), 64>>>();
    cand_kernel<<<(M_NODES * 32 + 255) / 256, 256>>>();
    refine_kernel<<<(M_NODES + 7) / 8, 256>>>(nodes_out, adj_out);
    cgemm64_kernel<<<dim3(M_NODES / 64, 2), 256>>>(nodes_out, We1);
    c3_kernel<<<729, 128>>>(We1, be1);
    edge_fused64_kernel<<<NE / 64, 256>>>(We2, be2, edges_out);
}